// round 1
// baseline (speedup 1.0000x reference)
#include <cuda_runtime.h>

#define NB  32
#define C1  64
#define C2  384
#define HH  56
#define HW  3136
#define EPSV 1e-5f

// ---------------- scratch (device globals; no allocation allowed) ----------------
__device__ float g_h  [(size_t)NB * C2 * HW];   // expand output (after BN+ReLU6)
__device__ float g_h2 [(size_t)NB * C2 * HW];   // dw output (after bias+BN+ReLU6)
__device__ float g_ctxsum[NB * C2];             // pooled sums (atomics)
__device__ float g_bias2 [NB * C2];             // scale2*ctx_bias + shift2
__device__ float g_s1[C2], g_sh1[C2];
__device__ float g_s2[C2], g_sh2[C2];
__device__ float g_s3[C1], g_sh3[C1];

// ---------------- prep: fold BN params, zero pool accumulators ----------------
__global__ void prep_kernel(const float* __restrict__ g1, const float* __restrict__ b1,
                            const float* __restrict__ m1, const float* __restrict__ v1,
                            const float* __restrict__ g2, const float* __restrict__ b2,
                            const float* __restrict__ m2, const float* __restrict__ v2,
                            const float* __restrict__ g3, const float* __restrict__ b3,
                            const float* __restrict__ m3, const float* __restrict__ v3)
{
    int t = threadIdx.x;
    if (t < C2) {
        float s = g1[t] * rsqrtf(v1[t] + EPSV);
        g_s1[t] = s; g_sh1[t] = b1[t] - m1[t] * s;
        float s2 = g2[t] * rsqrtf(v2[t] + EPSV);
        g_s2[t] = s2; g_sh2[t] = b2[t] - m2[t] * s2;
    }
    if (t < C1) {
        float s = g3[t] * rsqrtf(v3[t] + EPSV);
        g_s3[t] = s; g_sh3[t] = b3[t] - m3[t] * s;
    }
    for (int i = t; i < NB * C2; i += blockDim.x) g_ctxsum[i] = 0.f;
}

// ---------------- expand: 1x1 conv (GEMM 384x64 @ 64x3136 per n) + BN + ReLU6 + fused pool ----
// Tile: 128 pixels x 64 channels per c-tile; 128 threads; each thread 4 px x 16 ch.
__global__ void __launch_bounds__(128) expand_kernel(const float* __restrict__ x,
                                                     const float* __restrict__ w)
{
    extern __shared__ float sm[];
    float* xs = sm;              // [64][128]  k-major x tile
    float* ws = sm + 64 * 128;   // [64][68]   k-major w tile (padded row = 68)

    const int n    = blockIdx.y;
    const int pix0 = blockIdx.x * 128;
    const int t    = threadIdx.x;
    const int lane = t & 31;
    const int grp  = t >> 5;     // warp id 0..3 -> channel group

    const float* xn = x + (size_t)n * C1 * HW;

    // load x tile [64 k][128 px]
    #pragma unroll 4
    for (int k = 0; k < 64; ++k) {
        int p = pix0 + t;
        xs[k * 128 + t] = (p < HW) ? xn[(size_t)k * HW + p] : 0.f;
    }

    for (int ct = 0; ct < 6; ++ct) {
        const int cbase = ct * 64;
        __syncthreads();   // previous compute done (and orders xs on first iter)
        // load w tile: w[(cbase+c)*64 + k] -> ws[k][c]
        for (int i = t; i < 64 * 64; i += 128) {
            int c = i >> 6, k = i & 63;
            ws[k * 68 + c] = w[(cbase + c) * 64 + k];
        }
        __syncthreads();

        float acc[4][16];
        #pragma unroll
        for (int j = 0; j < 4; ++j)
            #pragma unroll
            for (int i = 0; i < 16; ++i) acc[j][i] = 0.f;

        #pragma unroll 4
        for (int k = 0; k < 64; ++k) {
            float xv[4];
            #pragma unroll
            for (int j = 0; j < 4; ++j) xv[j] = xs[k * 128 + lane + 32 * j];
            const float* wr = &ws[k * 68 + grp * 16];
            float4 w0 = *(const float4*)(wr + 0);
            float4 w1 = *(const float4*)(wr + 4);
            float4 w2 = *(const float4*)(wr + 8);
            float4 w3 = *(const float4*)(wr + 12);
            float wv[16] = { w0.x, w0.y, w0.z, w0.w, w1.x, w1.y, w1.z, w1.w,
                             w2.x, w2.y, w2.z, w2.w, w3.x, w3.y, w3.z, w3.w };
            #pragma unroll
            for (int j = 0; j < 4; ++j)
                #pragma unroll
                for (int i = 0; i < 16; ++i) acc[j][i] += xv[j] * wv[i];
        }

        // epilogue: BN1 + ReLU6 + store + fused pool partial (warp lanes = pixels)
        #pragma unroll
        for (int i = 0; i < 16; ++i) {
            int c = cbase + grp * 16 + i;
            float sc = g_s1[c], sh = g_sh1[c];
            float csum = 0.f;
            float* hp = g_h + ((size_t)(n * C2 + c)) * HW;
            #pragma unroll
            for (int j = 0; j < 4; ++j) {
                int p = pix0 + lane + 32 * j;
                float v = fminf(fmaxf(sc * acc[j][i] + sh, 0.f), 6.f);
                if (p < HW) { hp[p] = v; csum += v; }
            }
            #pragma unroll
            for (int off = 16; off > 0; off >>= 1)
                csum += __shfl_down_sync(0xffffffffu, csum, off);
            if (lane == 0) atomicAdd(&g_ctxsum[n * C2 + c], csum);
        }
    }
}

// ---------------- context bias: bias2[n,o] = s2[o]*(mean_c ctx * w_ctx[o,c]) + sh2[o] ----
__global__ void ctxbias_kernel(const float* __restrict__ wctx)
{
    __shared__ float cs[C2];
    const int n = blockIdx.x;
    const int o = threadIdx.x;
    cs[o] = g_ctxsum[n * C2 + o] * (1.f / (float)HW);
    __syncthreads();
    const float* wr = wctx + o * C2;
    float a = 0.f;
    #pragma unroll 4
    for (int c = 0; c < C2; ++c) a += cs[c] * wr[c];
    g_bias2[n * C2 + o] = g_s2[o] * a + g_sh2[o];
}

// ---------------- depthwise 3x3 + ctx bias + BN2 + ReLU6 ----------------
__global__ void __launch_bounds__(256) dw_kernel(const float* __restrict__ wdw)
{
    const int n = blockIdx.z;
    const int c = blockIdx.y;
    const int pix = blockIdx.x * 256 + threadIdx.x;

    __shared__ float wd[9];
    __shared__ float bias_s, sc_s;
    if (threadIdx.x < 9) wd[threadIdx.x] = wdw[c * 9 + threadIdx.x];
    if (threadIdx.x == 0) { bias_s = g_bias2[n * C2 + c]; sc_s = g_s2[c]; }
    __syncthreads();
    if (pix >= HW) return;

    const float* hp = g_h + ((size_t)(n * C2 + c)) * HW;
    const int r = pix / HH;
    const int col = pix - r * HH;

    float s = 0.f;
    #pragma unroll
    for (int dr = -1; dr <= 1; ++dr) {
        int rr = r + dr;
        if ((unsigned)rr < HH) {
            const float* row = hp + rr * HH;
            #pragma unroll
            for (int dc = -1; dc <= 1; ++dc) {
                int cc = col + dc;
                if ((unsigned)cc < HH) s += row[cc] * wd[(dr + 1) * 3 + (dc + 1)];
            }
        }
    }
    float v = fminf(fmaxf(sc_s * s + bias_s, 0.f), 6.f);
    g_h2[((size_t)(n * C2 + c)) * HW + pix] = v;
}

// ---------------- project: GEMM 64x384 @ 384x3136 + BN3 + residual ----------------
__global__ void __launch_bounds__(128) project_kernel(const float* __restrict__ x,
                                                      const float* __restrict__ wp,
                                                      float* __restrict__ out)
{
    extern __shared__ float sm[];
    float* hs = sm;              // [64][128]
    float* ws = sm + 64 * 128;   // [64][68]

    const int n    = blockIdx.y;
    const int pix0 = blockIdx.x * 128;
    const int t    = threadIdx.x;
    const int lane = t & 31;
    const int grp  = t >> 5;

    float acc[4][16];
    #pragma unroll
    for (int j = 0; j < 4; ++j)
        #pragma unroll
        for (int i = 0; i < 16; ++i) acc[j][i] = 0.f;

    for (int kt = 0; kt < 6; ++kt) {
        const int kbase = kt * 64;
        __syncthreads();
        const float* hb = g_h2 + ((size_t)n * C2 + kbase) * HW;
        #pragma unroll 4
        for (int k = 0; k < 64; ++k) {
            int p = pix0 + t;
            hs[k * 128 + t] = (p < HW) ? hb[(size_t)k * HW + p] : 0.f;
        }
        for (int i = t; i < 64 * 64; i += 128) {
            int c = i >> 6, k = i & 63;
            ws[k * 68 + c] = wp[c * C2 + kbase + k];
        }
        __syncthreads();

        #pragma unroll 4
        for (int k = 0; k < 64; ++k) {
            float xv[4];
            #pragma unroll
            for (int j = 0; j < 4; ++j) xv[j] = hs[k * 128 + lane + 32 * j];
            const float* wr = &ws[k * 68 + grp * 16];
            float4 w0 = *(const float4*)(wr + 0);
            float4 w1 = *(const float4*)(wr + 4);
            float4 w2 = *(const float4*)(wr + 8);
            float4 w3 = *(const float4*)(wr + 12);
            float wv[16] = { w0.x, w0.y, w0.z, w0.w, w1.x, w1.y, w1.z, w1.w,
                             w2.x, w2.y, w2.z, w2.w, w3.x, w3.y, w3.z, w3.w };
            #pragma unroll
            for (int j = 0; j < 4; ++j)
                #pragma unroll
                for (int i = 0; i < 16; ++i) acc[j][i] += xv[j] * wv[i];
        }
    }

    // epilogue: BN3 + residual
    #pragma unroll
    for (int i = 0; i < 16; ++i) {
        int c = grp * 16 + i;
        float sc = g_s3[c], sh = g_sh3[c];
        const float* xp = x   + ((size_t)(n * C1 + c)) * HW;
        float*       op = out + ((size_t)(n * C1 + c)) * HW;
        #pragma unroll
        for (int j = 0; j < 4; ++j) {
            int p = pix0 + lane + 32 * j;
            if (p < HW) op[p] = sc * acc[j][i] + sh + xp[p];
        }
    }
}

// ---------------- launch ----------------
extern "C" void kernel_launch(void* const* d_in, const int* in_sizes, int n_in,
                              void* d_out, int out_size)
{
    const float* x        = (const float*)d_in[0];
    const float* w_expand = (const float*)d_in[1];
    const float* g1 = (const float*)d_in[2];
    const float* b1 = (const float*)d_in[3];
    const float* m1 = (const float*)d_in[4];
    const float* v1 = (const float*)d_in[5];
    const float* w_dw  = (const float*)d_in[6];
    const float* w_ctx = (const float*)d_in[7];
    const float* g2 = (const float*)d_in[8];
    const float* b2 = (const float*)d_in[9];
    const float* m2 = (const float*)d_in[10];
    const float* v2 = (const float*)d_in[11];
    const float* w_proj = (const float*)d_in[12];
    const float* g3 = (const float*)d_in[13];
    const float* b3 = (const float*)d_in[14];
    const float* m3 = (const float*)d_in[15];
    const float* v3 = (const float*)d_in[16];
    float* out = (float*)d_out;

    const int smem_bytes = (64 * 128 + 64 * 68) * (int)sizeof(float); // 50176
    cudaFuncSetAttribute((const void*)expand_kernel,
                         cudaFuncAttributeMaxDynamicSharedMemorySize, smem_bytes);
    cudaFuncSetAttribute((const void*)project_kernel,
                         cudaFuncAttributeMaxDynamicSharedMemorySize, smem_bytes);

    prep_kernel<<<1, 512>>>(g1, b1, m1, v1, g2, b2, m2, v2, g3, b3, m3, v3);
    expand_kernel<<<dim3(25, NB), 128, smem_bytes>>>(x, w_expand);
    ctxbias_kernel<<<NB, C2>>>(w_ctx);
    dw_kernel<<<dim3(13, C2, NB), 256>>>(w_dw);
    project_kernel<<<dim3(25, NB), 128, smem_bytes>>>(x, w_proj, out);
}

// round 2
// speedup vs baseline: 1.4676x; 1.4676x over previous
#include <cuda_runtime.h>

#define NB  32
#define C1  64
#define C2  384
#define HH  56
#define HW  3136
#define EPSV 1e-5f

typedef unsigned long long u64;

__device__ __forceinline__ u64 pack2(float lo, float hi) {
    u64 r; asm("mov.b64 %0,{%1,%2};" : "=l"(r) : "f"(lo), "f"(hi)); return r;
}
__device__ __forceinline__ void fma2(u64& d, u64 a, u64 b) {
    asm("fma.rn.f32x2 %0,%1,%2,%0;" : "+l"(d) : "l"(a), "l"(b));
}
__device__ __forceinline__ void unpack2(u64 v, float& lo, float& hi) {
    asm("mov.b64 {%0,%1},%2;" : "=f"(lo), "=f"(hi) : "l"(v));
}

// ---------------- scratch (device globals; no allocation allowed) ----------------
__device__ float g_h  [(size_t)NB * C2 * HW];   // expand output (after BN+ReLU6)
__device__ float g_h2 [(size_t)NB * C2 * HW];   // dw output (after bias+BN+ReLU6)
__device__ float g_ctxsum[NB * C2];             // pooled sums (atomics)
__device__ float g_bias2 [NB * C2];             // scale2*ctx_bias + shift2
__device__ float g_s1[C2], g_sh1[C2];
__device__ float g_s2[C2], g_sh2[C2];
__device__ float g_s3[C1], g_sh3[C1];

// ---------------- prep: fold BN params, zero pool accumulators ----------------
__global__ void prep_kernel(const float* __restrict__ g1, const float* __restrict__ b1,
                            const float* __restrict__ m1, const float* __restrict__ v1,
                            const float* __restrict__ g2, const float* __restrict__ b2,
                            const float* __restrict__ m2, const float* __restrict__ v2,
                            const float* __restrict__ g3, const float* __restrict__ b3,
                            const float* __restrict__ m3, const float* __restrict__ v3)
{
    int t = threadIdx.x;
    if (t < C2) {
        float s = g1[t] * rsqrtf(v1[t] + EPSV);
        g_s1[t] = s; g_sh1[t] = b1[t] - m1[t] * s;
        float s2 = g2[t] * rsqrtf(v2[t] + EPSV);
        g_s2[t] = s2; g_sh2[t] = b2[t] - m2[t] * s2;
    }
    if (t < C1) {
        float s = g3[t] * rsqrtf(v3[t] + EPSV);
        g_s3[t] = s; g_sh3[t] = b3[t] - m3[t] * s;
    }
    for (int i = t; i < NB * C2; i += blockDim.x) g_ctxsum[i] = 0.f;
}

// ---------------- expand: 1x1 conv + BN1 + ReLU6 + fused pool ----------------
// Tile: 128 px x 64 ch; 128 threads; each thread 4 px x 16 ch (8 channel pairs, f32x2).
__global__ void __launch_bounds__(128) expand_kernel(const float* __restrict__ x,
                                                     const float* __restrict__ w)
{
    extern __shared__ float sm[];
    float* xs = sm;              // [64][128]  k-major x tile
    float* ws = sm + 64 * 128;   // [64][68]   k-major w tile (padded row = 68)

    const int n    = blockIdx.y;
    const int pix0 = blockIdx.x * 128;
    const int t    = threadIdx.x;
    const int lane = t & 31;
    const int grp  = t >> 5;     // warp id -> channel group

    const float* xn = x + (size_t)n * C1 * HW;

    #pragma unroll 4
    for (int k = 0; k < 64; ++k) {
        int p = pix0 + t;
        xs[k * 128 + t] = (p < HW) ? xn[(size_t)k * HW + p] : 0.f;
    }

    for (int ct = 0; ct < 6; ++ct) {
        const int cbase = ct * 64;
        __syncthreads();
        for (int i = t; i < 64 * 64; i += 128) {
            int c = i >> 6, k = i & 63;
            ws[k * 68 + c] = w[(cbase + c) * 64 + k];
        }
        __syncthreads();

        u64 acc[4][8];
        #pragma unroll
        for (int j = 0; j < 4; ++j)
            #pragma unroll
            for (int i = 0; i < 8; ++i) acc[j][i] = 0ull;

        #pragma unroll 2
        for (int k = 0; k < 64; ++k) {
            u64 xd[4];
            #pragma unroll
            for (int j = 0; j < 4; ++j) {
                float xv = xs[k * 128 + lane + 32 * j];
                xd[j] = pack2(xv, xv);
            }
            const u64* wr = (const u64*)&ws[k * 68 + grp * 16];
            u64 wv[8];
            #pragma unroll
            for (int i = 0; i < 8; ++i) wv[i] = wr[i];
            #pragma unroll
            for (int j = 0; j < 4; ++j)
                #pragma unroll
                for (int i = 0; i < 8; ++i) fma2(acc[j][i], xd[j], wv[i]);
        }

        // epilogue: BN1 + ReLU6 + store + fused pool partial
        #pragma unroll
        for (int i = 0; i < 8; ++i) {
            int c = cbase + grp * 16 + 2 * i;
            float sc0 = g_s1[c],     sh0 = g_sh1[c];
            float sc1 = g_s1[c + 1], sh1 = g_sh1[c + 1];
            float sum0 = 0.f, sum1 = 0.f;
            float* hp0 = g_h + ((size_t)(n * C2 + c)) * HW;
            float* hp1 = hp0 + HW;
            #pragma unroll
            for (int j = 0; j < 4; ++j) {
                float a0, a1; unpack2(acc[j][i], a0, a1);
                int p = pix0 + lane + 32 * j;
                float v0 = fminf(fmaxf(sc0 * a0 + sh0, 0.f), 6.f);
                float v1 = fminf(fmaxf(sc1 * a1 + sh1, 0.f), 6.f);
                if (p < HW) { hp0[p] = v0; hp1[p] = v1; sum0 += v0; sum1 += v1; }
            }
            #pragma unroll
            for (int off = 16; off > 0; off >>= 1) {
                sum0 += __shfl_down_sync(0xffffffffu, sum0, off);
                sum1 += __shfl_down_sync(0xffffffffu, sum1, off);
            }
            if (lane == 0) {
                atomicAdd(&g_ctxsum[n * C2 + c],     sum0);
                atomicAdd(&g_ctxsum[n * C2 + c + 1], sum1);
            }
        }
    }
}

// ---------------- context bias ----------------
__global__ void ctxbias_kernel(const float* __restrict__ wctx)
{
    __shared__ float cs[C2];
    const int n = blockIdx.x;
    const int o = threadIdx.x;
    cs[o] = g_ctxsum[n * C2 + o] * (1.f / (float)HW);
    __syncthreads();
    const float* wr = wctx + o * C2;
    float a = 0.f;
    #pragma unroll 4
    for (int c = 0; c < C2; ++c) a += cs[c] * wr[c];
    g_bias2[n * C2 + o] = g_s2[o] * a + g_sh2[o];
}

// ---------------- depthwise 3x3 + ctx bias + BN2 + ReLU6 (per-plane smem) ----------------
__global__ void __launch_bounds__(224) dw_kernel(const float* __restrict__ wdw)
{
    __shared__ float sp[HW];
    __shared__ float wd[9];
    __shared__ float bias_s, sc_s;

    const int c = blockIdx.x;
    const int n = blockIdx.y;
    const int t = threadIdx.x;

    const float* hp = g_h + ((size_t)(n * C2 + c)) * HW;

    // coalesced float4 plane load (1 LDG per element instead of 9)
    const float4* src = (const float4*)hp;
    float4* dst = (float4*)sp;
    #pragma unroll
    for (int i = t; i < HW / 4; i += 224) dst[i] = src[i];
    if (t < 9) wd[t] = wdw[c * 9 + t];
    if (t == 0) { bias_s = g_bias2[n * C2 + c]; sc_s = g_s2[c]; }
    __syncthreads();

    const int col = t % HH;       // 224 = 4 * 56
    const int r0  = t / HH;       // 0..3
    const bool cl = (col > 0), cr = (col < HH - 1);
    float* outp = g_h2 + ((size_t)(n * C2 + c)) * HW;

    #pragma unroll
    for (int j = 0; j < 14; ++j) {
        const int r = r0 + 4 * j;
        const float* rc = sp + r * HH + col;
        float s = 0.f;
        if (r > 0) {
            const float* rm = rc - HH;
            if (cl) s += rm[-1] * wd[0];
            s += rm[0] * wd[1];
            if (cr) s += rm[1] * wd[2];
        }
        if (cl) s += rc[-1] * wd[3];
        s += rc[0] * wd[4];
        if (cr) s += rc[1] * wd[5];
        if (r < HH - 1) {
            const float* rp = rc + HH;
            if (cl) s += rp[-1] * wd[6];
            s += rp[0] * wd[7];
            if (cr) s += rp[1] * wd[8];
        }
        float v = fminf(fmaxf(sc_s * s + bias_s, 0.f), 6.f);
        outp[r * HH + col] = v;
    }
}

// ---------------- project: GEMM + BN3 + residual ----------------
__global__ void __launch_bounds__(128) project_kernel(const float* __restrict__ x,
                                                      const float* __restrict__ wp,
                                                      float* __restrict__ out)
{
    extern __shared__ float sm[];
    float* hs = sm;              // [64][128]
    float* ws = sm + 64 * 128;   // [64][68]

    const int n    = blockIdx.y;
    const int pix0 = blockIdx.x * 128;
    const int t    = threadIdx.x;
    const int lane = t & 31;
    const int grp  = t >> 5;

    u64 acc[4][8];
    #pragma unroll
    for (int j = 0; j < 4; ++j)
        #pragma unroll
        for (int i = 0; i < 8; ++i) acc[j][i] = 0ull;

    for (int kt = 0; kt < 6; ++kt) {
        const int kbase = kt * 64;
        __syncthreads();
        const float* hb = g_h2 + ((size_t)n * C2 + kbase) * HW;
        #pragma unroll 4
        for (int k = 0; k < 64; ++k) {
            int p = pix0 + t;
            hs[k * 128 + t] = (p < HW) ? hb[(size_t)k * HW + p] : 0.f;
        }
        for (int i = t; i < 64 * 64; i += 128) {
            int c = i >> 6, k = i & 63;
            ws[k * 68 + c] = wp[c * C2 + kbase + k];
        }
        __syncthreads();

        #pragma unroll 2
        for (int k = 0; k < 64; ++k) {
            u64 xd[4];
            #pragma unroll
            for (int j = 0; j < 4; ++j) {
                float xv = hs[k * 128 + lane + 32 * j];
                xd[j] = pack2(xv, xv);
            }
            const u64* wr = (const u64*)&ws[k * 68 + grp * 16];
            u64 wv[8];
            #pragma unroll
            for (int i = 0; i < 8; ++i) wv[i] = wr[i];
            #pragma unroll
            for (int j = 0; j < 4; ++j)
                #pragma unroll
                for (int i = 0; i < 8; ++i) fma2(acc[j][i], xd[j], wv[i]);
        }
    }

    // epilogue: BN3 + residual
    #pragma unroll
    for (int i = 0; i < 8; ++i) {
        int c = grp * 16 + 2 * i;
        float sc0 = g_s3[c],     sh0 = g_sh3[c];
        float sc1 = g_s3[c + 1], sh1 = g_sh3[c + 1];
        const float* xp0 = x   + ((size_t)(n * C1 + c)) * HW;
        float*       op0 = out + ((size_t)(n * C1 + c)) * HW;
        const float* xp1 = xp0 + HW;
        float*       op1 = op0 + HW;
        #pragma unroll
        for (int j = 0; j < 4; ++j) {
            float a0, a1; unpack2(acc[j][i], a0, a1);
            int p = pix0 + lane + 32 * j;
            if (p < HW) {
                op0[p] = sc0 * a0 + sh0 + xp0[p];
                op1[p] = sc1 * a1 + sh1 + xp1[p];
            }
        }
    }
}

// ---------------- launch ----------------
extern "C" void kernel_launch(void* const* d_in, const int* in_sizes, int n_in,
                              void* d_out, int out_size)
{
    const float* x        = (const float*)d_in[0];
    const float* w_expand = (const float*)d_in[1];
    const float* g1 = (const float*)d_in[2];
    const float* b1 = (const float*)d_in[3];
    const float* m1 = (const float*)d_in[4];
    const float* v1 = (const float*)d_in[5];
    const float* w_dw  = (const float*)d_in[6];
    const float* w_ctx = (const float*)d_in[7];
    const float* g2 = (const float*)d_in[8];
    const float* b2 = (const float*)d_in[9];
    const float* m2 = (const float*)d_in[10];
    const float* v2 = (const float*)d_in[11];
    const float* w_proj = (const float*)d_in[12];
    const float* g3 = (const float*)d_in[13];
    const float* b3 = (const float*)d_in[14];
    const float* m3 = (const float*)d_in[15];
    const float* v3 = (const float*)d_in[16];
    float* out = (float*)d_out;

    const int smem_bytes = (64 * 128 + 64 * 68) * (int)sizeof(float); // 50176
    cudaFuncSetAttribute((const void*)expand_kernel,
                         cudaFuncAttributeMaxDynamicSharedMemorySize, smem_bytes);
    cudaFuncSetAttribute((const void*)project_kernel,
                         cudaFuncAttributeMaxDynamicSharedMemorySize, smem_bytes);

    prep_kernel<<<1, 512>>>(g1, b1, m1, v1, g2, b2, m2, v2, g3, b3, m3, v3);
    expand_kernel<<<dim3(25, NB), 128, smem_bytes>>>(x, w_expand);
    ctxbias_kernel<<<NB, C2>>>(w_ctx);
    dw_kernel<<<dim3(C2, NB), 224>>>(w_dw);
    project_kernel<<<dim3(25, NB), 128, smem_bytes>>>(x, w_proj, out);
}

// round 3
// speedup vs baseline: 1.9375x; 1.3201x over previous
#include <cuda_runtime.h>
#include <cuda_bf16.h>
#include <cstdint>

#define NB  32
#define C1  64
#define C2  384
#define HH  56
#define HW  3136
#define EPSV 1e-5f

// ---------------- scratch (device globals; no allocation allowed) ----------------
__device__ float g_h  [(size_t)NB * C2 * HW];   // expand output (after BN+ReLU6)
__device__ float g_h2 [(size_t)NB * C2 * HW];   // dw output (after bias+BN+ReLU6)
__device__ float g_ctxsum[NB * C2];             // pooled sums (atomics)
__device__ float g_bias2 [NB * C2];             // scale2*ctx_bias + shift2
__device__ float g_s1[C2], g_sh1[C2];
__device__ float g_s2[C2], g_sh2[C2];
__device__ float g_s3[C1], g_sh3[C1];

// ---------------- helpers ----------------
__device__ __forceinline__ void bsplit2(float f0, float f1, uint32_t& hi, uint32_t& lo) {
    // pack bf16(f0) in low half, bf16(f1) in high half; lo = bf16 of residuals
    __nv_bfloat16 h0 = __float2bfloat16_rn(f0);
    __nv_bfloat16 h1 = __float2bfloat16_rn(f1);
    float r0 = f0 - __bfloat162float(h0);
    float r1 = f1 - __bfloat162float(h1);
    __nv_bfloat162 H; H.x = h0; H.y = h1;
    __nv_bfloat162 L = __floats2bfloat162_rn(r0, r1);
    hi = *reinterpret_cast<uint32_t*>(&H);
    lo = *reinterpret_cast<uint32_t*>(&L);
}

__device__ __forceinline__ void mma16816(float* c, const uint32_t* a, const uint32_t* b) {
    asm volatile(
        "mma.sync.aligned.m16n8k16.row.col.f32.bf16.bf16.f32 "
        "{%0,%1,%2,%3},{%4,%5,%6,%7},{%8,%9},{%0,%1,%2,%3};"
        : "+f"(c[0]), "+f"(c[1]), "+f"(c[2]), "+f"(c[3])
        : "r"(a[0]), "r"(a[1]), "r"(a[2]), "r"(a[3]), "r"(b[0]), "r"(b[1]));
}

__device__ __forceinline__ float clip6(float v) { return fminf(fmaxf(v, 0.f), 6.f); }

// ---------------- prep ----------------
__global__ void prep_kernel(const float* __restrict__ g1, const float* __restrict__ b1,
                            const float* __restrict__ m1, const float* __restrict__ v1,
                            const float* __restrict__ g2, const float* __restrict__ b2,
                            const float* __restrict__ m2, const float* __restrict__ v2,
                            const float* __restrict__ g3, const float* __restrict__ b3,
                            const float* __restrict__ m3, const float* __restrict__ v3)
{
    int t = threadIdx.x;
    if (t < C2) {
        float s = g1[t] * rsqrtf(v1[t] + EPSV);
        g_s1[t] = s; g_sh1[t] = b1[t] - m1[t] * s;
        float s2 = g2[t] * rsqrtf(v2[t] + EPSV);
        g_s2[t] = s2; g_sh2[t] = b2[t] - m2[t] * s2;
    }
    if (t < C1) {
        float s = g3[t] * rsqrtf(v3[t] + EPSV);
        g_s3[t] = s; g_sh3[t] = b3[t] - m3[t] * s;
    }
    for (int i = t; i < NB * C2; i += blockDim.x) g_ctxsum[i] = 0.f;
}

// ======================= EXPAND: tensor-core GEMM + BN1 + ReLU6 + pool =====================
// D[c, p] = sum_k W[c,k] X[k,p] per batch n. Block: 256 thr (8 warps).
// Per-chunk tile: M=128 ch x N=128 px, K=64. 3 chunks. Warp tile 64x32 (wm in {0,1}, wn in 0..3).
// Smem word layout: row-stride 36 uint32; word j packs bf16(k=2j), bf16(k=2j+1).
#define XS_STRIDE 36
__global__ void __launch_bounds__(256) expand_kernel(const float* __restrict__ x,
                                                     const float* __restrict__ w)
{
    extern __shared__ uint32_t sm[];
    uint32_t* xsh = sm;                        // [128 px][36]
    uint32_t* xsl = xsh + 128 * XS_STRIDE;
    uint32_t* wsh = xsl + 128 * XS_STRIDE;     // [128 ch][36]
    uint32_t* wsl = wsh + 128 * XS_STRIDE;

    const int n    = blockIdx.y;
    const int pix0 = blockIdx.x * 128;
    const int tid  = threadIdx.x;
    const int wid  = tid >> 5;
    const int lane = tid & 31;
    const int g    = lane >> 2;
    const int tq   = lane & 3;
    const int wm   = wid & 1;     // 2 warps over M
    const int wn   = wid >> 1;    // 4 warps over N

    const float* xn = x + (size_t)n * C1 * HW;

    // ---- load X tile (once): word j <-> k = 2j, 2j+1 ----
    for (int idx = tid; idx < 128 * 32; idx += 256) {
        int j = idx >> 7;          // 0..31
        int p = idx & 127;         // 0..127
        int pg = pix0 + p;
        float f0 = 0.f, f1 = 0.f;
        if (pg < HW) {
            f0 = xn[(size_t)(2 * j) * HW + pg];
            f1 = xn[(size_t)(2 * j + 1) * HW + pg];
        }
        uint32_t hi, lo; bsplit2(f0, f1, hi, lo);
        xsh[p * XS_STRIDE + j] = hi;
        xsl[p * XS_STRIDE + j] = lo;
    }

    for (int ct = 0; ct < 3; ++ct) {
        const int cbase = ct * 128;
        __syncthreads();
        // ---- load W tile for this chunk ----
        for (int idx = tid; idx < 128 * 32; idx += 256) {
            int c = idx >> 5;      // 0..127
            int j = idx & 31;      // 0..31
            float2 wv = *(const float2*)(w + (size_t)(cbase + c) * 64 + 2 * j);
            uint32_t hi, lo; bsplit2(wv.x, wv.y, hi, lo);
            wsh[c * XS_STRIDE + j] = hi;
            wsl[c * XS_STRIDE + j] = lo;
        }
        __syncthreads();

        float acc[4][4][4];
        #pragma unroll
        for (int mt = 0; mt < 4; ++mt)
            #pragma unroll
            for (int nt = 0; nt < 4; ++nt)
                #pragma unroll
                for (int i = 0; i < 4; ++i) acc[mt][nt][i] = 0.f;

        #pragma unroll
        for (int s = 0; s < 4; ++s) {
            const int w0 = tq + 8 * s;      // a0/a1, b0
            const int w1 = tq + 4 + 8 * s;  // a2/a3, b1
            uint32_t ah[4][4], al[4][4];
            #pragma unroll
            for (int mt = 0; mt < 4; ++mt) {
                int r0 = (wm * 64 + mt * 16 + g) * XS_STRIDE;
                int r8 = r0 + 8 * XS_STRIDE;
                ah[mt][0] = wsh[r0 + w0]; ah[mt][1] = wsh[r8 + w0];
                ah[mt][2] = wsh[r0 + w1]; ah[mt][3] = wsh[r8 + w1];
                al[mt][0] = wsl[r0 + w0]; al[mt][1] = wsl[r8 + w0];
                al[mt][2] = wsl[r0 + w1]; al[mt][3] = wsl[r8 + w1];
            }
            uint32_t bh[4][2], bl[4][2];
            #pragma unroll
            for (int nt = 0; nt < 4; ++nt) {
                int r = (wn * 32 + nt * 8 + g) * XS_STRIDE;
                bh[nt][0] = xsh[r + w0]; bh[nt][1] = xsh[r + w1];
                bl[nt][0] = xsl[r + w0]; bl[nt][1] = xsl[r + w1];
            }
            #pragma unroll
            for (int mt = 0; mt < 4; ++mt)
                #pragma unroll
                for (int nt = 0; nt < 4; ++nt) {
                    mma16816(acc[mt][nt], ah[mt], bh[nt]);
                    mma16816(acc[mt][nt], ah[mt], bl[nt]);
                    mma16816(acc[mt][nt], al[mt], bh[nt]);
                }
        }

        // ---- epilogue: BN1 + ReLU6 + store + pool ----
        #pragma unroll
        for (int mt = 0; mt < 4; ++mt) {
            int c0 = cbase + wm * 64 + mt * 16 + g;
            int c8 = c0 + 8;
            float s0 = g_s1[c0], h0 = g_sh1[c0];
            float s8 = g_s1[c8], h8 = g_sh1[c8];
            float* hp0 = g_h + ((size_t)(n * C2 + c0)) * HW;
            float* hp8 = g_h + ((size_t)(n * C2 + c8)) * HW;
            float rs0 = 0.f, rs8 = 0.f;
            #pragma unroll
            for (int nt = 0; nt < 4; ++nt) {
                int p = pix0 + wn * 32 + nt * 8 + 2 * tq;
                float v00 = clip6(s0 * acc[mt][nt][0] + h0);
                float v01 = clip6(s0 * acc[mt][nt][1] + h0);
                float v10 = clip6(s8 * acc[mt][nt][2] + h8);
                float v11 = clip6(s8 * acc[mt][nt][3] + h8);
                if (p < HW) {
                    *(float2*)(hp0 + p) = make_float2(v00, v01);
                    *(float2*)(hp8 + p) = make_float2(v10, v11);
                    rs0 += v00 + v01; rs8 += v10 + v11;
                }
            }
            rs0 += __shfl_xor_sync(0xffffffffu, rs0, 1);
            rs0 += __shfl_xor_sync(0xffffffffu, rs0, 2);
            rs8 += __shfl_xor_sync(0xffffffffu, rs8, 1);
            rs8 += __shfl_xor_sync(0xffffffffu, rs8, 2);
            if (tq == 0) {
                atomicAdd(&g_ctxsum[n * C2 + c0], rs0);
                atomicAdd(&g_ctxsum[n * C2 + c8], rs8);
            }
        }
    }
}

// ---------------- context bias ----------------
__global__ void ctxbias_kernel(const float* __restrict__ wctx)
{
    __shared__ float cs[C2];
    const int n = blockIdx.x;
    const int o = threadIdx.x;
    cs[o] = g_ctxsum[n * C2 + o] * (1.f / (float)HW);
    __syncthreads();
    const float* wr = wctx + o * C2;
    float a = 0.f;
    #pragma unroll 4
    for (int c = 0; c < C2; ++c) a += cs[c] * wr[c];
    g_bias2[n * C2 + o] = g_s2[o] * a + g_sh2[o];
}

// ---------------- depthwise 3x3 + ctx bias + BN2 + ReLU6 (per-plane smem) ----------------
__global__ void __launch_bounds__(224) dw_kernel(const float* __restrict__ wdw)
{
    __shared__ float sp[HW];
    __shared__ float wd[9];
    __shared__ float bias_s, sc_s;

    const int c = blockIdx.x;
    const int n = blockIdx.y;
    const int t = threadIdx.x;

    const float* hp = g_h + ((size_t)(n * C2 + c)) * HW;
    const float4* src = (const float4*)hp;
    float4* dst = (float4*)sp;
    #pragma unroll
    for (int i = t; i < HW / 4; i += 224) dst[i] = src[i];
    if (t < 9) wd[t] = wdw[c * 9 + t];
    if (t == 0) { bias_s = g_bias2[n * C2 + c]; sc_s = g_s2[c]; }
    __syncthreads();

    const int col = t % HH;
    const int r0  = t / HH;
    const bool cl = (col > 0), cr = (col < HH - 1);
    float* outp = g_h2 + ((size_t)(n * C2 + c)) * HW;

    #pragma unroll
    for (int j = 0; j < 14; ++j) {
        const int r = r0 + 4 * j;
        const float* rc = sp + r * HH + col;
        float s = 0.f;
        if (r > 0) {
            const float* rm = rc - HH;
            if (cl) s += rm[-1] * wd[0];
            s += rm[0] * wd[1];
            if (cr) s += rm[1] * wd[2];
        }
        if (cl) s += rc[-1] * wd[3];
        s += rc[0] * wd[4];
        if (cr) s += rc[1] * wd[5];
        if (r < HH - 1) {
            const float* rp = rc + HH;
            if (cl) s += rp[-1] * wd[6];
            s += rp[0] * wd[7];
            if (cr) s += rp[1] * wd[8];
        }
        outp[r * HH + col] = clip6(sc_s * s + bias_s);
    }
}

// ======================= PROJECT: tensor-core GEMM + BN3 + residual ========================
// D[c, p] = sum_k Wp[c,k] H2[k,p]. M=64, N=128 px/block, K=384 (6 chunks of 64).
// 8 warps: wm in {0,1} (32 ch each, 2 mtiles), wn in 0..3 (32 px each, 4 ntiles).
__global__ void __launch_bounds__(256) project_kernel(const float* __restrict__ x,
                                                      const float* __restrict__ wp,
                                                      float* __restrict__ out)
{
    extern __shared__ uint32_t sm[];
    uint32_t* xsh = sm;                        // [128 px][36]
    uint32_t* xsl = xsh + 128 * XS_STRIDE;
    uint32_t* wsh = xsl + 128 * XS_STRIDE;     // [64 ch][36]
    uint32_t* wsl = wsh + 64 * XS_STRIDE;

    const int n    = blockIdx.y;
    const int pix0 = blockIdx.x * 128;
    const int tid  = threadIdx.x;
    const int wid  = tid >> 5;
    const int lane = tid & 31;
    const int g    = lane >> 2;
    const int tq   = lane & 3;
    const int wm   = wid & 1;
    const int wn   = wid >> 1;

    float acc[2][4][4];
    #pragma unroll
    for (int mt = 0; mt < 2; ++mt)
        #pragma unroll
        for (int nt = 0; nt < 4; ++nt)
            #pragma unroll
            for (int i = 0; i < 4; ++i) acc[mt][nt][i] = 0.f;

    for (int kt = 0; kt < 6; ++kt) {
        const int kbase = kt * 64;
        __syncthreads();
        // H2 tile
        const float* hb = g_h2 + ((size_t)n * C2 + kbase) * HW;
        for (int idx = tid; idx < 128 * 32; idx += 256) {
            int j = idx >> 7;
            int p = idx & 127;
            int pg = pix0 + p;
            float f0 = 0.f, f1 = 0.f;
            if (pg < HW) {
                f0 = hb[(size_t)(2 * j) * HW + pg];
                f1 = hb[(size_t)(2 * j + 1) * HW + pg];
            }
            uint32_t hi, lo; bsplit2(f0, f1, hi, lo);
            xsh[p * XS_STRIDE + j] = hi;
            xsl[p * XS_STRIDE + j] = lo;
        }
        // W tile
        for (int idx = tid; idx < 64 * 32; idx += 256) {
            int c = idx >> 5;
            int j = idx & 31;
            float2 wv = *(const float2*)(wp + (size_t)c * C2 + kbase + 2 * j);
            uint32_t hi, lo; bsplit2(wv.x, wv.y, hi, lo);
            wsh[c * XS_STRIDE + j] = hi;
            wsl[c * XS_STRIDE + j] = lo;
        }
        __syncthreads();

        #pragma unroll
        for (int s = 0; s < 4; ++s) {
            const int w0 = tq + 8 * s;
            const int w1 = tq + 4 + 8 * s;
            uint32_t ah[2][4], al[2][4];
            #pragma unroll
            for (int mt = 0; mt < 2; ++mt) {
                int r0 = (wm * 32 + mt * 16 + g) * XS_STRIDE;
                int r8 = r0 + 8 * XS_STRIDE;
                ah[mt][0] = wsh[r0 + w0]; ah[mt][1] = wsh[r8 + w0];
                ah[mt][2] = wsh[r0 + w1]; ah[mt][3] = wsh[r8 + w1];
                al[mt][0] = wsl[r0 + w0]; al[mt][1] = wsl[r8 + w0];
                al[mt][2] = wsl[r0 + w1]; al[mt][3] = wsl[r8 + w1];
            }
            uint32_t bh[4][2], bl[4][2];
            #pragma unroll
            for (int nt = 0; nt < 4; ++nt) {
                int r = (wn * 32 + nt * 8 + g) * XS_STRIDE;
                bh[nt][0] = xsh[r + w0]; bh[nt][1] = xsh[r + w1];
                bl[nt][0] = xsl[r + w0]; bl[nt][1] = xsl[r + w1];
            }
            #pragma unroll
            for (int mt = 0; mt < 2; ++mt)
                #pragma unroll
                for (int nt = 0; nt < 4; ++nt) {
                    mma16816(acc[mt][nt], ah[mt], bh[nt]);
                    mma16816(acc[mt][nt], ah[mt], bl[nt]);
                    mma16816(acc[mt][nt], al[mt], bh[nt]);
                }
        }
    }

    // epilogue: BN3 + residual
    #pragma unroll
    for (int mt = 0; mt < 2; ++mt) {
        int c0 = wm * 32 + mt * 16 + g;
        int c8 = c0 + 8;
        float s0 = g_s3[c0], h0 = g_sh3[c0];
        float s8 = g_s3[c8], h8 = g_sh3[c8];
        const float* xp0 = x   + ((size_t)(n * C1 + c0)) * HW;
        const float* xp8 = x   + ((size_t)(n * C1 + c8)) * HW;
        float*       op0 = out + ((size_t)(n * C1 + c0)) * HW;
        float*       op8 = out + ((size_t)(n * C1 + c8)) * HW;
        #pragma unroll
        for (int nt = 0; nt < 4; ++nt) {
            int p = pix0 + wn * 32 + nt * 8 + 2 * tq;
            if (p < HW) {
                float2 r0 = *(const float2*)(xp0 + p);
                float2 r8 = *(const float2*)(xp8 + p);
                *(float2*)(op0 + p) = make_float2(s0 * acc[mt][nt][0] + h0 + r0.x,
                                                  s0 * acc[mt][nt][1] + h0 + r0.y);
                *(float2*)(op8 + p) = make_float2(s8 * acc[mt][nt][2] + h8 + r8.x,
                                                  s8 * acc[mt][nt][3] + h8 + r8.y);
            }
        }
    }
}

// ---------------- launch ----------------
extern "C" void kernel_launch(void* const* d_in, const int* in_sizes, int n_in,
                              void* d_out, int out_size)
{
    const float* x        = (const float*)d_in[0];
    const float* w_expand = (const float*)d_in[1];
    const float* g1 = (const float*)d_in[2];
    const float* b1 = (const float*)d_in[3];
    const float* m1 = (const float*)d_in[4];
    const float* v1 = (const float*)d_in[5];
    const float* w_dw  = (const float*)d_in[6];
    const float* w_ctx = (const float*)d_in[7];
    const float* g2 = (const float*)d_in[8];
    const float* b2 = (const float*)d_in[9];
    const float* m2 = (const float*)d_in[10];
    const float* v2 = (const float*)d_in[11];
    const float* w_proj = (const float*)d_in[12];
    const float* g3 = (const float*)d_in[13];
    const float* b3 = (const float*)d_in[14];
    const float* m3 = (const float*)d_in[15];
    const float* v3 = (const float*)d_in[16];
    float* out = (float*)d_out;

    const int smem_expand  = 4 * 128 * XS_STRIDE * 4;           // 73728
    const int smem_project = (2 * 128 + 2 * 64) * XS_STRIDE * 4; // 55296
    cudaFuncSetAttribute((const void*)expand_kernel,
                         cudaFuncAttributeMaxDynamicSharedMemorySize, smem_expand);
    cudaFuncSetAttribute((const void*)project_kernel,
                         cudaFuncAttributeMaxDynamicSharedMemorySize, smem_project);

    prep_kernel<<<1, 512>>>(g1, b1, m1, v1, g2, b2, m2, v2, g3, b3, m3, v3);
    expand_kernel<<<dim3(25, NB), 256, smem_expand>>>(x, w_expand);
    ctxbias_kernel<<<NB, C2>>>(w_ctx);
    dw_kernel<<<dim3(C2, NB), 224>>>(w_dw);
    project_kernel<<<dim3(25, NB), 256, smem_project>>>(x, w_proj, out);
}

// round 4
// speedup vs baseline: 2.0113x; 1.0381x over previous
#include <cuda_runtime.h>
#include <cuda_bf16.h>
#include <cstdint>

#define NB  32
#define C1  64
#define C2  384
#define HH  56
#define HW  3136
#define EPSV 1e-5f
#define XS  36            // smem row stride in 32-bit words (conflict-free for ldmatrix)

// ---------------- scratch (device globals; no allocation allowed) ----------------
__device__ float    g_h   [(size_t)NB * C2 * HW];       // expand output fp32 (dw input)
__device__ uint32_t g_h2h [(size_t)NB * 192 * HW];      // dw output, packed bf16 hi (ch pair/word)
__device__ uint32_t g_h2l [(size_t)NB * 192 * HW];      // dw output, packed bf16 lo
__device__ uint32_t g_weh [384 * 32], g_wel[384 * 32];  // w_expand split-packed [c][j]
__device__ uint32_t g_wph [64 * 192], g_wpl[64 * 192];  // w_proj   split-packed [c][j]
__device__ float g_ctxsum[NB * C2];
__device__ float g_bias2 [NB * C2];
__device__ float g_s1[C2], g_sh1[C2];
__device__ float g_s2[C2], g_sh2[C2];
__device__ float g_s3[C1], g_sh3[C1];

// ---------------- helpers ----------------
__device__ __forceinline__ void bsplit2(float f0, float f1, uint32_t& hi, uint32_t& lo) {
    __nv_bfloat16 h0 = __float2bfloat16_rn(f0);
    __nv_bfloat16 h1 = __float2bfloat16_rn(f1);
    float r0 = f0 - __bfloat162float(h0);
    float r1 = f1 - __bfloat162float(h1);
    __nv_bfloat162 H; H.x = h0; H.y = h1;
    __nv_bfloat162 L = __floats2bfloat162_rn(r0, r1);
    hi = *reinterpret_cast<uint32_t*>(&H);
    lo = *reinterpret_cast<uint32_t*>(&L);
}

__device__ __forceinline__ void mma16816(float* c, const uint32_t* a, uint32_t b0, uint32_t b1) {
    asm volatile(
        "mma.sync.aligned.m16n8k16.row.col.f32.bf16.bf16.f32 "
        "{%0,%1,%2,%3},{%4,%5,%6,%7},{%8,%9},{%0,%1,%2,%3};"
        : "+f"(c[0]), "+f"(c[1]), "+f"(c[2]), "+f"(c[3])
        : "r"(a[0]), "r"(a[1]), "r"(a[2]), "r"(a[3]), "r"(b0), "r"(b1));
}

__device__ __forceinline__ void ldsm4(uint32_t* r, uint32_t addr) {
    asm volatile("ldmatrix.sync.aligned.m8n8.x4.shared.b16 {%0,%1,%2,%3},[%4];"
                 : "=r"(r[0]), "=r"(r[1]), "=r"(r[2]), "=r"(r[3]) : "r"(addr));
}

__device__ __forceinline__ float clip6(float v) { return fminf(fmaxf(v, 0.f), 6.f); }

// ---------------- prep: fold BN, zero pool, pre-split weights ----------------
__global__ void prep_kernel(const float* __restrict__ g1, const float* __restrict__ b1,
                            const float* __restrict__ m1, const float* __restrict__ v1,
                            const float* __restrict__ g2, const float* __restrict__ b2,
                            const float* __restrict__ m2, const float* __restrict__ v2,
                            const float* __restrict__ g3, const float* __restrict__ b3,
                            const float* __restrict__ m3, const float* __restrict__ v3,
                            const float* __restrict__ we, const float* __restrict__ wpj)
{
    int t = threadIdx.x;
    if (t < C2) {
        float s = g1[t] * rsqrtf(v1[t] + EPSV);
        g_s1[t] = s; g_sh1[t] = b1[t] - m1[t] * s;
        float s2 = g2[t] * rsqrtf(v2[t] + EPSV);
        g_s2[t] = s2; g_sh2[t] = b2[t] - m2[t] * s2;
    }
    if (t < C1) {
        float s = g3[t] * rsqrtf(v3[t] + EPSV);
        g_s3[t] = s; g_sh3[t] = b3[t] - m3[t] * s;
    }
    for (int i = t; i < NB * C2; i += blockDim.x) g_ctxsum[i] = 0.f;
    for (int i = t; i < 384 * 32; i += blockDim.x) {
        float2 wv = *(const float2*)(we + (size_t)i * 2);
        bsplit2(wv.x, wv.y, g_weh[i], g_wel[i]);
    }
    for (int i = t; i < 64 * 192; i += blockDim.x) {
        float2 wv = *(const float2*)(wpj + (size_t)i * 2);
        bsplit2(wv.x, wv.y, g_wph[i], g_wpl[i]);
    }
}

// ======================= EXPAND =====================
// Block: 256 thr, tile M=64 ch x N=128 px, K=64 full. 6 M-chunks; X tile loaded once.
// Warps: wm in {0,1} x wn in {0..3}; warp tile 32x32 (2 mtiles x 4 ntiles).
__global__ void __launch_bounds__(256, 2) expand_kernel(const float* __restrict__ x)
{
    extern __shared__ uint32_t sm[];
    uint32_t* xsh = sm;                    // [128 px][XS]
    uint32_t* xsl = xsh + 128 * XS;
    uint32_t* wsh = xsl + 128 * XS;        // [64 ch][XS]
    uint32_t* wsl = wsh + 64 * XS;

    const int n    = blockIdx.y;
    const int pix0 = blockIdx.x * 128;
    const int tid  = threadIdx.x;
    const int wid  = tid >> 5;
    const int lane = tid & 31;
    const int g    = lane >> 2;
    const int tq   = lane & 3;
    const int wm   = wid & 1;
    const int wn   = wid >> 1;

    const uint32_t xshb = (uint32_t)__cvta_generic_to_shared(xsh);
    const uint32_t xslb = (uint32_t)__cvta_generic_to_shared(xsl);
    const uint32_t wshb = (uint32_t)__cvta_generic_to_shared(wsh);
    const uint32_t wslb = (uint32_t)__cvta_generic_to_shared(wsl);
    const int lrow = (lane & 7) + ((lane >> 3) & 1) * 8;
    const int loff = (lrow * XS + ((lane >> 4) * 4)) * 4;   // per-lane byte offset in tile

    const float* xn = x + (size_t)n * C1 * HW;

    // ---- X tile (once): word j packs k=2j,2j+1 ----
    for (int idx = tid; idx < 128 * 32; idx += 256) {
        int j = idx >> 7, p = idx & 127;
        int pg = pix0 + p;
        float f0 = 0.f, f1 = 0.f;
        if (pg < HW) {
            f0 = xn[(size_t)(2 * j) * HW + pg];
            f1 = xn[(size_t)(2 * j + 1) * HW + pg];
        }
        uint32_t hi, lo; bsplit2(f0, f1, hi, lo);
        xsh[p * XS + j] = hi;
        xsl[p * XS + j] = lo;
    }

    for (int ct = 0; ct < 6; ++ct) {
        const int cbase = ct * 64;
        __syncthreads();
        for (int idx = tid; idx < 64 * 32; idx += 256) {
            int c = idx >> 5, j = idx & 31;
            wsh[c * XS + j] = g_weh[(cbase + c) * 32 + j];
            wsl[c * XS + j] = g_wel[(cbase + c) * 32 + j];
        }
        __syncthreads();

        float acc[2][4][4];
        #pragma unroll
        for (int mt = 0; mt < 2; ++mt)
            #pragma unroll
            for (int nt = 0; nt < 4; ++nt)
                #pragma unroll
                for (int i = 0; i < 4; ++i) acc[mt][nt][i] = 0.f;

        #pragma unroll
        for (int s = 0; s < 4; ++s) {
            const int soff = s * 32;   // 8 words * 4B
            uint32_t ah[2][4], al[2][4], bh[2][4], bl[2][4];
            #pragma unroll
            for (int mt = 0; mt < 2; ++mt) {
                uint32_t off = (uint32_t)((wm * 32 + mt * 16) * XS * 4 + soff) + loff;
                ldsm4(ah[mt], wshb + off);
                ldsm4(al[mt], wslb + off);
            }
            #pragma unroll
            for (int q = 0; q < 2; ++q) {
                uint32_t off = (uint32_t)((wn * 32 + q * 16) * XS * 4 + soff) + loff;
                ldsm4(bh[q], xshb + off);
                ldsm4(bl[q], xslb + off);
            }
            #pragma unroll
            for (int mt = 0; mt < 2; ++mt)
                #pragma unroll
                for (int q = 0; q < 2; ++q) {
                    // ntile 2q: regs {r0,r2}; ntile 2q+1: {r1,r3}
                    mma16816(acc[mt][2*q],   ah[mt], bh[q][0], bh[q][2]);
                    mma16816(acc[mt][2*q],   ah[mt], bl[q][0], bl[q][2]);
                    mma16816(acc[mt][2*q],   al[mt], bh[q][0], bh[q][2]);
                    mma16816(acc[mt][2*q+1], ah[mt], bh[q][1], bh[q][3]);
                    mma16816(acc[mt][2*q+1], ah[mt], bl[q][1], bl[q][3]);
                    mma16816(acc[mt][2*q+1], al[mt], bh[q][1], bh[q][3]);
                }
        }

        // ---- epilogue: BN1 + ReLU6 + store + pool ----
        #pragma unroll
        for (int mt = 0; mt < 2; ++mt) {
            int c0 = cbase + wm * 32 + mt * 16 + g;
            int c8 = c0 + 8;
            float s0 = g_s1[c0], h0 = g_sh1[c0];
            float s8 = g_s1[c8], h8 = g_sh1[c8];
            float* hp0 = g_h + ((size_t)(n * C2 + c0)) * HW;
            float* hp8 = g_h + ((size_t)(n * C2 + c8)) * HW;
            float rs0 = 0.f, rs8 = 0.f;
            #pragma unroll
            for (int nt = 0; nt < 4; ++nt) {
                int p = pix0 + wn * 32 + nt * 8 + 2 * tq;
                float v00 = clip6(s0 * acc[mt][nt][0] + h0);
                float v01 = clip6(s0 * acc[mt][nt][1] + h0);
                float v10 = clip6(s8 * acc[mt][nt][2] + h8);
                float v11 = clip6(s8 * acc[mt][nt][3] + h8);
                if (p < HW) {
                    *(float2*)(hp0 + p) = make_float2(v00, v01);
                    *(float2*)(hp8 + p) = make_float2(v10, v11);
                    rs0 += v00 + v01; rs8 += v10 + v11;
                }
            }
            rs0 += __shfl_xor_sync(0xffffffffu, rs0, 1);
            rs0 += __shfl_xor_sync(0xffffffffu, rs0, 2);
            rs8 += __shfl_xor_sync(0xffffffffu, rs8, 1);
            rs8 += __shfl_xor_sync(0xffffffffu, rs8, 2);
            if (tq == 0) {
                atomicAdd(&g_ctxsum[n * C2 + c0], rs0);
                atomicAdd(&g_ctxsum[n * C2 + c8], rs8);
            }
        }
    }
}

// ---------------- context bias ----------------
__global__ void ctxbias_kernel(const float* __restrict__ wctx)
{
    __shared__ float cs[C2];
    const int n = blockIdx.x;
    const int o = threadIdx.x;
    cs[o] = g_ctxsum[n * C2 + o] * (1.f / (float)HW);
    __syncthreads();
    const float* wr = wctx + o * C2;
    float a = 0.f;
    #pragma unroll 4
    for (int c = 0; c < C2; ++c) a += cs[c] * wr[c];
    g_bias2[n * C2 + o] = g_s2[o] * a + g_sh2[o];
}

// ---------------- depthwise 3x3 (channel PAIR per block) + bias + BN2 + ReLU6, split output ----
__global__ void __launch_bounds__(224) dw_kernel(const float* __restrict__ wdw)
{
    __shared__ float sp0[HW];
    __shared__ float sp1[HW];
    __shared__ float wd[18];
    __shared__ float bs[2], sc[2];

    const int jw = blockIdx.x;         // word / channel-pair index 0..191
    const int n  = blockIdx.y;
    const int t  = threadIdx.x;
    const int c0 = 2 * jw;

    const float4* src0 = (const float4*)(g_h + ((size_t)(n * C2 + c0)) * HW);
    const float4* src1 = (const float4*)(g_h + ((size_t)(n * C2 + c0 + 1)) * HW);
    float4* d0 = (float4*)sp0;
    float4* d1 = (float4*)sp1;
    #pragma unroll
    for (int i = t; i < HW / 4; i += 224) { d0[i] = src0[i]; d1[i] = src1[i]; }
    if (t < 18) wd[t] = wdw[c0 * 9 + t];
    if (t < 2)  { bs[t] = g_bias2[n * C2 + c0 + t]; sc[t] = g_s2[c0 + t]; }
    __syncthreads();

    const int col = t % HH;
    const int r0  = t / HH;
    const bool cl = (col > 0), cr = (col < HH - 1);
    uint32_t* oh = g_h2h + ((size_t)(n * 192 + jw)) * HW;
    uint32_t* ol = g_h2l + ((size_t)(n * 192 + jw)) * HW;
    const float b0 = bs[0], b1 = bs[1], s0 = sc[0], s1 = sc[1];

    #pragma unroll
    for (int j = 0; j < 14; ++j) {
        const int r = r0 + 4 * j;
        const float* rc0 = sp0 + r * HH + col;
        const float* rc1 = sp1 + r * HH + col;
        float a0 = 0.f, a1 = 0.f;
        if (r > 0) {
            if (cl) { a0 += rc0[-HH-1] * wd[0]; a1 += rc1[-HH-1] * wd[9]; }
            a0 += rc0[-HH] * wd[1]; a1 += rc1[-HH] * wd[10];
            if (cr) { a0 += rc0[-HH+1] * wd[2]; a1 += rc1[-HH+1] * wd[11]; }
        }
        if (cl) { a0 += rc0[-1] * wd[3]; a1 += rc1[-1] * wd[12]; }
        a0 += rc0[0] * wd[4]; a1 += rc1[0] * wd[13];
        if (cr) { a0 += rc0[1] * wd[5]; a1 += rc1[1] * wd[14]; }
        if (r < HH - 1) {
            if (cl) { a0 += rc0[HH-1] * wd[6]; a1 += rc1[HH-1] * wd[15]; }
            a0 += rc0[HH] * wd[7]; a1 += rc1[HH] * wd[16];
            if (cr) { a0 += rc0[HH+1] * wd[8]; a1 += rc1[HH+1] * wd[17]; }
        }
        float v0 = clip6(s0 * a0 + b0);
        float v1 = clip6(s1 * a1 + b1);
        uint32_t hi, lo; bsplit2(v0, v1, hi, lo);
        oh[r * HH + col] = hi;
        ol[r * HH + col] = lo;
    }
}

// ======================= PROJECT =====================
// M=64 ch x N=128 px, K=384 (6 chunks of 64). Same warp layout as expand.
__global__ void __launch_bounds__(256, 2) project_kernel(const float* __restrict__ x,
                                                         float* __restrict__ out)
{
    extern __shared__ uint32_t sm[];
    uint32_t* xsh = sm;                    // [128 px][XS]
    uint32_t* xsl = xsh + 128 * XS;
    uint32_t* wsh = xsl + 128 * XS;        // [64 ch][XS]
    uint32_t* wsl = wsh + 64 * XS;

    const int n    = blockIdx.y;
    const int pix0 = blockIdx.x * 128;
    const int tid  = threadIdx.x;
    const int wid  = tid >> 5;
    const int lane = tid & 31;
    const int g    = lane >> 2;
    const int tq   = lane & 3;
    const int wm   = wid & 1;
    const int wn   = wid >> 1;

    const uint32_t xshb = (uint32_t)__cvta_generic_to_shared(xsh);
    const uint32_t xslb = (uint32_t)__cvta_generic_to_shared(xsl);
    const uint32_t wshb = (uint32_t)__cvta_generic_to_shared(wsh);
    const uint32_t wslb = (uint32_t)__cvta_generic_to_shared(wsl);
    const int lrow = (lane & 7) + ((lane >> 3) & 1) * 8;
    const int loff = (lrow * XS + ((lane >> 4) * 4)) * 4;

    float acc[2][4][4];
    #pragma unroll
    for (int mt = 0; mt < 2; ++mt)
        #pragma unroll
        for (int nt = 0; nt < 4; ++nt)
            #pragma unroll
            for (int i = 0; i < 4; ++i) acc[mt][nt][i] = 0.f;

    for (int kt = 0; kt < 6; ++kt) {
        __syncthreads();
        const uint32_t* hb = g_h2h + ((size_t)(n * 192 + kt * 32)) * HW;
        const uint32_t* lb = g_h2l + ((size_t)(n * 192 + kt * 32)) * HW;
        for (int idx = tid; idx < 128 * 32; idx += 256) {
            int j = idx >> 7, p = idx & 127;
            int pg = pix0 + p;
            uint32_t hi = 0, lo = 0;
            if (pg < HW) {
                hi = hb[(size_t)j * HW + pg];
                lo = lb[(size_t)j * HW + pg];
            }
            xsh[p * XS + j] = hi;
            xsl[p * XS + j] = lo;
        }
        for (int idx = tid; idx < 64 * 32; idx += 256) {
            int c = idx >> 5, j = idx & 31;
            wsh[c * XS + j] = g_wph[c * 192 + kt * 32 + j];
            wsl[c * XS + j] = g_wpl[c * 192 + kt * 32 + j];
        }
        __syncthreads();

        #pragma unroll
        for (int s = 0; s < 4; ++s) {
            const int soff = s * 32;
            uint32_t ah[2][4], al[2][4], bh[2][4], bl[2][4];
            #pragma unroll
            for (int mt = 0; mt < 2; ++mt) {
                uint32_t off = (uint32_t)((wm * 32 + mt * 16) * XS * 4 + soff) + loff;
                ldsm4(ah[mt], wshb + off);
                ldsm4(al[mt], wslb + off);
            }
            #pragma unroll
            for (int q = 0; q < 2; ++q) {
                uint32_t off = (uint32_t)((wn * 32 + q * 16) * XS * 4 + soff) + loff;
                ldsm4(bh[q], xshb + off);
                ldsm4(bl[q], xslb + off);
            }
            #pragma unroll
            for (int mt = 0; mt < 2; ++mt)
                #pragma unroll
                for (int q = 0; q < 2; ++q) {
                    mma16816(acc[mt][2*q],   ah[mt], bh[q][0], bh[q][2]);
                    mma16816(acc[mt][2*q],   ah[mt], bl[q][0], bl[q][2]);
                    mma16816(acc[mt][2*q],   al[mt], bh[q][0], bh[q][2]);
                    mma16816(acc[mt][2*q+1], ah[mt], bh[q][1], bh[q][3]);
                    mma16816(acc[mt][2*q+1], ah[mt], bl[q][1], bl[q][3]);
                    mma16816(acc[mt][2*q+1], al[mt], bh[q][1], bh[q][3]);
                }
        }
    }

    // epilogue: BN3 + residual
    #pragma unroll
    for (int mt = 0; mt < 2; ++mt) {
        int c0 = wm * 32 + mt * 16 + g;
        int c8 = c0 + 8;
        float s0 = g_s3[c0], h0 = g_sh3[c0];
        float s8 = g_s3[c8], h8 = g_sh3[c8];
        const float* xp0 = x   + ((size_t)(n * C1 + c0)) * HW;
        const float* xp8 = x   + ((size_t)(n * C1 + c8)) * HW;
        float*       op0 = out + ((size_t)(n * C1 + c0)) * HW;
        float*       op8 = out + ((size_t)(n * C1 + c8)) * HW;
        #pragma unroll
        for (int nt = 0; nt < 4; ++nt) {
            int p = pix0 + wn * 32 + nt * 8 + 2 * tq;
            if (p < HW) {
                float2 r0 = *(const float2*)(xp0 + p);
                float2 r8 = *(const float2*)(xp8 + p);
                *(float2*)(op0 + p) = make_float2(s0 * acc[mt][nt][0] + h0 + r0.x,
                                                  s0 * acc[mt][nt][1] + h0 + r0.y);
                *(float2*)(op8 + p) = make_float2(s8 * acc[mt][nt][2] + h8 + r8.x,
                                                  s8 * acc[mt][nt][3] + h8 + r8.y);
            }
        }
    }
}

// ---------------- launch ----------------
extern "C" void kernel_launch(void* const* d_in, const int* in_sizes, int n_in,
                              void* d_out, int out_size)
{
    const float* x        = (const float*)d_in[0];
    const float* w_expand = (const float*)d_in[1];
    const float* g1 = (const float*)d_in[2];
    const float* b1 = (const float*)d_in[3];
    const float* m1 = (const float*)d_in[4];
    const float* v1 = (const float*)d_in[5];
    const float* w_dw  = (const float*)d_in[6];
    const float* w_ctx = (const float*)d_in[7];
    const float* g2 = (const float*)d_in[8];
    const float* b2 = (const float*)d_in[9];
    const float* m2 = (const float*)d_in[10];
    const float* v2 = (const float*)d_in[11];
    const float* w_proj = (const float*)d_in[12];
    const float* g3 = (const float*)d_in[13];
    const float* b3 = (const float*)d_in[14];
    const float* m3 = (const float*)d_in[15];
    const float* v3 = (const float*)d_in[16];
    float* out = (float*)d_out;

    const int smem_gemm = (2 * 128 * XS + 2 * 64 * XS) * (int)sizeof(uint32_t); // 55296
    cudaFuncSetAttribute((const void*)expand_kernel,
                         cudaFuncAttributeMaxDynamicSharedMemorySize, smem_gemm);
    cudaFuncSetAttribute((const void*)project_kernel,
                         cudaFuncAttributeMaxDynamicSharedMemorySize, smem_gemm);

    prep_kernel<<<1, 512>>>(g1, b1, m1, v1, g2, b2, m2, v2, g3, b3, m3, v3,
                            w_expand, w_proj);
    expand_kernel<<<dim3(25, NB), 256, smem_gemm>>>(x);
    ctxbias_kernel<<<NB, C2>>>(w_ctx);
    dw_kernel<<<dim3(192, NB), 224>>>(w_dw);
    project_kernel<<<dim3(25, NB), 256, smem_gemm>>>(x, out);
}

// round 6
// speedup vs baseline: 2.2506x; 1.1190x over previous
#include <cuda_runtime.h>
#include <cuda_fp16.h>
#include <cstdint>

#define NB  32
#define C1  64
#define C2  384
#define HH  56
#define HW  3136
#define EPSV 1e-5f
#define XS  36            // smem row stride in 32-bit words (conflict-free for ldmatrix)

// ---------------- scratch (device globals; no allocation allowed) ----------------
__device__ __half   g_hf  [(size_t)NB * C2 * HW];     // expand output fp16 planes (dw input)
__device__ uint32_t g_h2  [(size_t)NB * 192 * HW];    // dw output, packed fp16 ch-pair words
__device__ uint32_t g_weh [384 * 32], g_wel[384 * 32]; // w_expand split fp16-pair words [c][j]
__device__ uint32_t g_wph [64 * 192], g_wpl[64 * 192]; // w_proj   split fp16-pair words [c][j]
__device__ float g_ctxsum[NB * C2];
__device__ float g_bias2 [NB * C2];
__device__ float g_s1[C2], g_sh1[C2];
__device__ float g_s2[C2], g_sh2[C2];
__device__ float g_s3[C1], g_sh3[C1];

// ---------------- helpers ----------------
__device__ __forceinline__ void hsplit2(float f0, float f1, uint32_t& hi, uint32_t& lo) {
    __half h0 = __float2half_rn(f0);
    __half h1 = __float2half_rn(f1);
    float r0 = f0 - __half2float(h0);
    float r1 = f1 - __half2float(h1);
    __half2 H; H.x = h0; H.y = h1;
    __half2 L; L.x = __float2half_rn(r0); L.y = __float2half_rn(r1);
    hi = *reinterpret_cast<uint32_t*>(&H);
    lo = *reinterpret_cast<uint32_t*>(&L);
}
__device__ __forceinline__ uint32_t hpack2(float f0, float f1) {
    __half2 H = __floats2half2_rn(f0, f1);
    return *reinterpret_cast<uint32_t*>(&H);
}

__device__ __forceinline__ void mma16816(float* c, const uint32_t* a, uint32_t b0, uint32_t b1) {
    asm volatile(
        "mma.sync.aligned.m16n8k16.row.col.f32.f16.f16.f32 "
        "{%0,%1,%2,%3},{%4,%5,%6,%7},{%8,%9},{%0,%1,%2,%3};"
        : "+f"(c[0]), "+f"(c[1]), "+f"(c[2]), "+f"(c[3])
        : "r"(a[0]), "r"(a[1]), "r"(a[2]), "r"(a[3]), "r"(b0), "r"(b1));
}

__device__ __forceinline__ void ldsm4(uint32_t* r, uint32_t addr) {
    asm volatile("ldmatrix.sync.aligned.m8n8.x4.shared.b16 {%0,%1,%2,%3},[%4];"
                 : "=r"(r[0]), "=r"(r[1]), "=r"(r[2]), "=r"(r[3]) : "r"(addr));
}

__device__ __forceinline__ float clip6(float v) { return fminf(fmaxf(v, 0.f), 6.f); }

// ---------------- prep: fold BN, zero pool, pre-split weights (fp16 hi/lo) ----------------
__global__ void prep_kernel(const float* __restrict__ g1, const float* __restrict__ b1,
                            const float* __restrict__ m1, const float* __restrict__ v1,
                            const float* __restrict__ g2, const float* __restrict__ b2,
                            const float* __restrict__ m2, const float* __restrict__ v2,
                            const float* __restrict__ g3, const float* __restrict__ b3,
                            const float* __restrict__ m3, const float* __restrict__ v3,
                            const float* __restrict__ we, const float* __restrict__ wpj)
{
    int t = threadIdx.x;
    if (t < C2) {
        float s = g1[t] * rsqrtf(v1[t] + EPSV);
        g_s1[t] = s; g_sh1[t] = b1[t] - m1[t] * s;
        float s2 = g2[t] * rsqrtf(v2[t] + EPSV);
        g_s2[t] = s2; g_sh2[t] = b2[t] - m2[t] * s2;
    }
    if (t < C1) {
        float s = g3[t] * rsqrtf(v3[t] + EPSV);
        g_s3[t] = s; g_sh3[t] = b3[t] - m3[t] * s;
    }
    for (int i = t; i < NB * C2; i += blockDim.x) g_ctxsum[i] = 0.f;
    for (int i = t; i < 384 * 32; i += blockDim.x) {
        float2 wv = *(const float2*)(we + (size_t)i * 2);
        hsplit2(wv.x, wv.y, g_weh[i], g_wel[i]);
    }
    for (int i = t; i < 64 * 192; i += blockDim.x) {
        float2 wv = *(const float2*)(wpj + (size_t)i * 2);
        hsplit2(wv.x, wv.y, g_wph[i], g_wpl[i]);
    }
}

// ======================= EXPAND =====================
// D[c,p] = sum_k W[c,k] X[k,p]. Block 256 thr; tile M=64 ch x N=128 px, K=64; 6 M-chunks.
// A = W (hi+lo terms), B = X (single fp16). Warp tile 32x32.
__global__ void __launch_bounds__(256, 2) expand_kernel(const float* __restrict__ x)
{
    extern __shared__ uint32_t sm[];
    uint32_t* xsh = sm;                    // [128 px][XS]  X fp16-pair words
    uint32_t* wsh = xsh + 128 * XS;        // [64 ch][XS]   W hi
    uint32_t* wsl = wsh + 64 * XS;         // [64 ch][XS]   W lo

    const int n    = blockIdx.y;
    const int pix0 = blockIdx.x * 128;
    const int tid  = threadIdx.x;
    const int wid  = tid >> 5;
    const int lane = tid & 31;
    const int g    = lane >> 2;
    const int tq   = lane & 3;
    const int wm   = wid & 1;
    const int wn   = wid >> 1;

    const uint32_t xshb = (uint32_t)__cvta_generic_to_shared(xsh);
    const uint32_t wshb = (uint32_t)__cvta_generic_to_shared(wsh);
    const uint32_t wslb = (uint32_t)__cvta_generic_to_shared(wsl);
    const int lrow = (lane & 7) + ((lane >> 3) & 1) * 8;
    const int loff = (lrow * XS + ((lane >> 4) * 4)) * 4;

    const float* xn = x + (size_t)n * C1 * HW;

    // ---- X tile (once): word j packs k=2j,2j+1 as fp16 ----
    for (int idx = tid; idx < 128 * 32; idx += 256) {
        int j = idx >> 7, p = idx & 127;
        int pg = pix0 + p;
        float f0 = 0.f, f1 = 0.f;
        if (pg < HW) {
            f0 = xn[(size_t)(2 * j) * HW + pg];
            f1 = xn[(size_t)(2 * j + 1) * HW + pg];
        }
        xsh[p * XS + j] = hpack2(f0, f1);
    }

    for (int ct = 0; ct < 6; ++ct) {
        const int cbase = ct * 64;
        __syncthreads();
        for (int idx = tid; idx < 64 * 32; idx += 256) {
            int c = idx >> 5, j = idx & 31;
            wsh[c * XS + j] = g_weh[(cbase + c) * 32 + j];
            wsl[c * XS + j] = g_wel[(cbase + c) * 32 + j];
        }
        __syncthreads();

        float acc[2][4][4];
        #pragma unroll
        for (int mt = 0; mt < 2; ++mt)
            #pragma unroll
            for (int nt = 0; nt < 4; ++nt)
                #pragma unroll
                for (int i = 0; i < 4; ++i) acc[mt][nt][i] = 0.f;

        #pragma unroll
        for (int s = 0; s < 4; ++s) {
            const int soff = s * 32;
            uint32_t ah[2][4], al[2][4], bh[2][4];
            #pragma unroll
            for (int mt = 0; mt < 2; ++mt) {
                uint32_t off = (uint32_t)((wm * 32 + mt * 16) * XS * 4 + soff) + loff;
                ldsm4(ah[mt], wshb + off);
                ldsm4(al[mt], wslb + off);
            }
            #pragma unroll
            for (int q = 0; q < 2; ++q) {
                uint32_t off = (uint32_t)((wn * 32 + q * 16) * XS * 4 + soff) + loff;
                ldsm4(bh[q], xshb + off);
            }
            #pragma unroll
            for (int mt = 0; mt < 2; ++mt)
                #pragma unroll
                for (int q = 0; q < 2; ++q) {
                    mma16816(acc[mt][2*q],   ah[mt], bh[q][0], bh[q][2]);
                    mma16816(acc[mt][2*q],   al[mt], bh[q][0], bh[q][2]);
                    mma16816(acc[mt][2*q+1], ah[mt], bh[q][1], bh[q][3]);
                    mma16816(acc[mt][2*q+1], al[mt], bh[q][1], bh[q][3]);
                }
        }

        // ---- epilogue: BN1 + ReLU6 + fp16 store + pool ----
        #pragma unroll
        for (int mt = 0; mt < 2; ++mt) {
            int c0 = cbase + wm * 32 + mt * 16 + g;
            int c8 = c0 + 8;
            float s0 = g_s1[c0], h0 = g_sh1[c0];
            float s8 = g_s1[c8], h8 = g_sh1[c8];
            __half* hp0 = g_hf + ((size_t)(n * C2 + c0)) * HW;
            __half* hp8 = g_hf + ((size_t)(n * C2 + c8)) * HW;
            float rs0 = 0.f, rs8 = 0.f;
            #pragma unroll
            for (int nt = 0; nt < 4; ++nt) {
                int p = pix0 + wn * 32 + nt * 8 + 2 * tq;
                float v00 = clip6(s0 * acc[mt][nt][0] + h0);
                float v01 = clip6(s0 * acc[mt][nt][1] + h0);
                float v10 = clip6(s8 * acc[mt][nt][2] + h8);
                float v11 = clip6(s8 * acc[mt][nt][3] + h8);
                if (p < HW) {
                    *(__half2*)(hp0 + p) = __floats2half2_rn(v00, v01);
                    *(__half2*)(hp8 + p) = __floats2half2_rn(v10, v11);
                    rs0 += v00 + v01; rs8 += v10 + v11;
                }
            }
            rs0 += __shfl_xor_sync(0xffffffffu, rs0, 1);
            rs0 += __shfl_xor_sync(0xffffffffu, rs0, 2);
            rs8 += __shfl_xor_sync(0xffffffffu, rs8, 1);
            rs8 += __shfl_xor_sync(0xffffffffu, rs8, 2);
            if (tq == 0) {
                atomicAdd(&g_ctxsum[n * C2 + c0], rs0);
                atomicAdd(&g_ctxsum[n * C2 + c8], rs8);
            }
        }
    }
}

// ---------------- context bias ----------------
__global__ void ctxbias_kernel(const float* __restrict__ wctx)
{
    __shared__ float cs[C2];
    const int n = blockIdx.x;
    const int o = threadIdx.x;
    cs[o] = g_ctxsum[n * C2 + o] * (1.f / (float)HW);
    __syncthreads();
    const float* wr = wctx + o * C2;
    float a = 0.f;
    #pragma unroll 4
    for (int c = 0; c < C2; ++c) a += cs[c] * wr[c];
    g_bias2[n * C2 + o] = g_s2[o] * a + g_sh2[o];
}

// ---------------- depthwise 3x3 (channel pair/block) + bias + BN2 + ReLU6 ----------------
__global__ void __launch_bounds__(224) dw_kernel(const float* __restrict__ wdw)
{
    __shared__ float sp0[HW];
    __shared__ float sp1[HW];
    __shared__ float wd[18];
    __shared__ float bs[2], sc[2];

    const int jw = blockIdx.x;         // channel-pair index 0..191
    const int n  = blockIdx.y;
    const int t  = threadIdx.x;
    const int c0 = 2 * jw;

    // load two fp16 planes, convert to fp32 in smem
    const uint4* src0 = (const uint4*)(g_hf + ((size_t)(n * C2 + c0)) * HW);
    const uint4* src1 = (const uint4*)(g_hf + ((size_t)(n * C2 + c0 + 1)) * HW);
    #pragma unroll
    for (int i = t; i < HW / 8; i += 224) {            // 392 uint4 per plane
        uint4 a = src0[i];
        uint4 b = src1[i];
        const __half2* ah = (const __half2*)&a;
        const __half2* bh = (const __half2*)&b;
        #pragma unroll
        for (int k = 0; k < 4; ++k) {
            float2 fa = __half22float2(ah[k]);
            float2 fb = __half22float2(bh[k]);
            sp0[8 * i + 2 * k]     = fa.x;
            sp0[8 * i + 2 * k + 1] = fa.y;
            sp1[8 * i + 2 * k]     = fb.x;
            sp1[8 * i + 2 * k + 1] = fb.y;
        }
    }
    if (t < 18) wd[t] = wdw[c0 * 9 + t];
    if (t < 2)  { bs[t] = g_bias2[n * C2 + c0 + t]; sc[t] = g_s2[c0 + t]; }
    __syncthreads();

    const int col = t % HH;
    const int r0  = t / HH;
    const bool cl = (col > 0), cr = (col < HH - 1);
    uint32_t* op = g_h2 + ((size_t)(n * 192 + jw)) * HW;
    const float b0 = bs[0], b1 = bs[1], s0 = sc[0], s1 = sc[1];

    #pragma unroll
    for (int j = 0; j < 14; ++j) {
        const int r = r0 + 4 * j;
        const float* rc0 = sp0 + r * HH + col;
        const float* rc1 = sp1 + r * HH + col;
        float a0 = 0.f, a1 = 0.f;
        if (r > 0) {
            if (cl) { a0 += rc0[-HH-1] * wd[0]; a1 += rc1[-HH-1] * wd[9]; }
            a0 += rc0[-HH] * wd[1]; a1 += rc1[-HH] * wd[10];
            if (cr) { a0 += rc0[-HH+1] * wd[2]; a1 += rc1[-HH+1] * wd[11]; }
        }
        if (cl) { a0 += rc0[-1] * wd[3]; a1 += rc1[-1] * wd[12]; }
        a0 += rc0[0] * wd[4]; a1 += rc1[0] * wd[13];
        if (cr) { a0 += rc0[1] * wd[5]; a1 += rc1[1] * wd[14]; }
        if (r < HH - 1) {
            if (cl) { a0 += rc0[HH-1] * wd[6]; a1 += rc1[HH-1] * wd[15]; }
            a0 += rc0[HH] * wd[7]; a1 += rc1[HH] * wd[16];
            if (cr) { a0 += rc0[HH+1] * wd[8]; a1 += rc1[HH+1] * wd[17]; }
        }
        float v0 = clip6(s0 * a0 + b0);
        float v1 = clip6(s1 * a1 + b1);
        op[r * HH + col] = hpack2(v0, v1);
    }
}

// ======================= PROJECT =====================
// D[c,p] = sum_k Wp[c,k] H2[k,p]. M=64, N=128 px, K=384 (6 chunks).
// A = Wp (hi+lo), B = H2 (single fp16, already packed).
__global__ void __launch_bounds__(256, 2) project_kernel(const float* __restrict__ x,
                                                         float* __restrict__ out)
{
    extern __shared__ uint32_t sm[];
    uint32_t* xsh = sm;                    // [128 px][XS]
    uint32_t* wsh = xsh + 128 * XS;        // [64 ch][XS]
    uint32_t* wsl = wsh + 64 * XS;

    const int n    = blockIdx.y;
    const int pix0 = blockIdx.x * 128;
    const int tid  = threadIdx.x;
    const int wid  = tid >> 5;
    const int lane = tid & 31;
    const int g    = lane >> 2;
    const int tq   = lane & 3;
    const int wm   = wid & 1;
    const int wn   = wid >> 1;

    const uint32_t xshb = (uint32_t)__cvta_generic_to_shared(xsh);
    const uint32_t wshb = (uint32_t)__cvta_generic_to_shared(wsh);
    const uint32_t wslb = (uint32_t)__cvta_generic_to_shared(wsl);
    const int lrow = (lane & 7) + ((lane >> 3) & 1) * 8;
    const int loff = (lrow * XS + ((lane >> 4) * 4)) * 4;

    float acc[2][4][4];
    #pragma unroll
    for (int mt = 0; mt < 2; ++mt)
        #pragma unroll
        for (int nt = 0; nt < 4; ++nt)
            #pragma unroll
            for (int i = 0; i < 4; ++i) acc[mt][nt][i] = 0.f;

    for (int kt = 0; kt < 6; ++kt) {
        __syncthreads();
        const uint32_t* hb = g_h2 + ((size_t)(n * 192 + kt * 32)) * HW;
        for (int idx = tid; idx < 128 * 32; idx += 256) {
            int j = idx >> 7, p = idx & 127;
            int pg = pix0 + p;
            xsh[p * XS + j] = (pg < HW) ? hb[(size_t)j * HW + pg] : 0u;
        }
        for (int idx = tid; idx < 64 * 32; idx += 256) {
            int c = idx >> 5, j = idx & 31;
            wsh[c * XS + j] = g_wph[c * 192 + kt * 32 + j];
            wsl[c * XS + j] = g_wpl[c * 192 + kt * 32 + j];
        }
        __syncthreads();

        #pragma unroll
        for (int s = 0; s < 4; ++s) {
            const int soff = s * 32;
            uint32_t ah[2][4], al[2][4], bh[2][4];
            #pragma unroll
            for (int mt = 0; mt < 2; ++mt) {
                uint32_t off = (uint32_t)((wm * 32 + mt * 16) * XS * 4 + soff) + loff;
                ldsm4(ah[mt], wshb + off);
                ldsm4(al[mt], wslb + off);
            }
            #pragma unroll
            for (int q = 0; q < 2; ++q) {
                uint32_t off = (uint32_t)((wn * 32 + q * 16) * XS * 4 + soff) + loff;
                ldsm4(bh[q], xshb + off);
            }
            #pragma unroll
            for (int mt = 0; mt < 2; ++mt)
                #pragma unroll
                for (int q = 0; q < 2; ++q) {
                    mma16816(acc[mt][2*q],   ah[mt], bh[q][0], bh[q][2]);
                    mma16816(acc[mt][2*q],   al[mt], bh[q][0], bh[q][2]);
                    mma16816(acc[mt][2*q+1], ah[mt], bh[q][1], bh[q][3]);
                    mma16816(acc[mt][2*q+1], al[mt], bh[q][1], bh[q][3]);
                }
        }
    }

    // epilogue: BN3 + residual
    #pragma unroll
    for (int mt = 0; mt < 2; ++mt) {
        int c0 = wm * 32 + mt * 16 + g;
        int c8 = c0 + 8;
        float s0 = g_s3[c0], h0 = g_sh3[c0];
        float s8 = g_s3[c8], h8 = g_sh3[c8];
        const float* xp0 = x   + ((size_t)(n * C1 + c0)) * HW;
        const float* xp8 = x   + ((size_t)(n * C1 + c8)) * HW;
        float*       op0 = out + ((size_t)(n * C1 + c0)) * HW;
        float*       op8 = out + ((size_t)(n * C1 + c8)) * HW;
        #pragma unroll
        for (int nt = 0; nt < 4; ++nt) {
            int p = pix0 + wn * 32 + nt * 8 + 2 * tq;
            if (p < HW) {
                float2 r0 = *(const float2*)(xp0 + p);
                float2 r8 = *(const float2*)(xp8 + p);
                *(float2*)(op0 + p) = make_float2(s0 * acc[mt][nt][0] + h0 + r0.x,
                                                  s0 * acc[mt][nt][1] + h0 + r0.y);
                *(float2*)(op8 + p) = make_float2(s8 * acc[mt][nt][2] + h8 + r8.x,
                                                  s8 * acc[mt][nt][3] + h8 + r8.y);
            }
        }
    }
}

// ---------------- launch ----------------
extern "C" void kernel_launch(void* const* d_in, const int* in_sizes, int n_in,
                              void* d_out, int out_size)
{
    const float* x        = (const float*)d_in[0];
    const float* w_expand = (const float*)d_in[1];
    const float* g1 = (const float*)d_in[2];
    const float* b1 = (const float*)d_in[3];
    const float* m1 = (const float*)d_in[4];
    const float* v1 = (const float*)d_in[5];
    const float* w_dw  = (const float*)d_in[6];
    const float* w_ctx = (const float*)d_in[7];
    const float* g2 = (const float*)d_in[8];
    const float* b2 = (const float*)d_in[9];
    const float* m2 = (const float*)d_in[10];
    const float* v2 = (const float*)d_in[11];
    const float* w_proj = (const float*)d_in[12];
    const float* g3 = (const float*)d_in[13];
    const float* b3 = (const float*)d_in[14];
    const float* m3 = (const float*)d_in[15];
    const float* v3 = (const float*)d_in[16];
    float* out = (float*)d_out;

    const int smem_gemm = (128 * XS + 2 * 64 * XS) * (int)sizeof(uint32_t); // 36864
    cudaFuncSetAttribute((const void*)expand_kernel,
                         cudaFuncAttributeMaxDynamicSharedMemorySize, smem_gemm);
    cudaFuncSetAttribute((const void*)project_kernel,
                         cudaFuncAttributeMaxDynamicSharedMemorySize, smem_gemm);

    prep_kernel<<<1, 512>>>(g1, b1, m1, v1, g2, b2, m2, v2, g3, b3, m3, v3,
                            w_expand, w_proj);
    expand_kernel<<<dim3(25, NB), 256, smem_gemm>>>(x);
    ctxbias_kernel<<<NB, C2>>>(w_ctx);
    dw_kernel<<<dim3(192, NB), 224>>>(w_dw);
    project_kernel<<<dim3(25, NB), 256, smem_gemm>>>(x, out);
}

// round 7
// speedup vs baseline: 2.4579x; 1.0921x over previous
#include <cuda_runtime.h>
#include <cuda_fp16.h>
#include <cstdint>

#define NB  32
#define C1  64
#define C2  384
#define HH  56
#define HW  3136
#define EPSV 1e-5f
#define XS  36            // smem row stride in 32-bit words (conflict-free for ldmatrix)

// ---------------- scratch (device globals; no allocation allowed) ----------------
__device__ __half   g_hf  [(size_t)NB * C2 * HW];     // expand output fp16 planes (dw input)
__device__ uint32_t g_h2  [(size_t)NB * 192 * HW];    // dw output, packed fp16 ch-pair words
__device__ uint32_t g_weh [384 * 32], g_wel[384 * 32]; // w_expand split fp16-pair words [c][j]
__device__ uint32_t g_wph [64 * 192];                  // w_proj single fp16-pair words [c][j]
__device__ float g_ctxsum[NB * C2];
__device__ float g_bias2 [NB * C2];
__device__ float g_s1[C2], g_sh1[C2];
__device__ float g_s2[C2], g_sh2[C2];
__device__ float g_s3[C1], g_sh3[C1];

// ---------------- helpers ----------------
__device__ __forceinline__ void hsplit2(float f0, float f1, uint32_t& hi, uint32_t& lo) {
    __half h0 = __float2half_rn(f0);
    __half h1 = __float2half_rn(f1);
    float r0 = f0 - __half2float(h0);
    float r1 = f1 - __half2float(h1);
    __half2 H; H.x = h0; H.y = h1;
    __half2 L; L.x = __float2half_rn(r0); L.y = __float2half_rn(r1);
    hi = *reinterpret_cast<uint32_t*>(&H);
    lo = *reinterpret_cast<uint32_t*>(&L);
}
__device__ __forceinline__ uint32_t hpack2(float f0, float f1) {
    __half2 H = __floats2half2_rn(f0, f1);
    return *reinterpret_cast<uint32_t*>(&H);
}

__device__ __forceinline__ void mma16816(float* c, const uint32_t* a, uint32_t b0, uint32_t b1) {
    asm volatile(
        "mma.sync.aligned.m16n8k16.row.col.f32.f16.f16.f32 "
        "{%0,%1,%2,%3},{%4,%5,%6,%7},{%8,%9},{%0,%1,%2,%3};"
        : "+f"(c[0]), "+f"(c[1]), "+f"(c[2]), "+f"(c[3])
        : "r"(a[0]), "r"(a[1]), "r"(a[2]), "r"(a[3]), "r"(b0), "r"(b1));
}

__device__ __forceinline__ void ldsm4(uint32_t* r, uint32_t addr) {
    asm volatile("ldmatrix.sync.aligned.m8n8.x4.shared.b16 {%0,%1,%2,%3},[%4];"
                 : "=r"(r[0]), "=r"(r[1]), "=r"(r[2]), "=r"(r[3]) : "r"(addr));
}

__device__ __forceinline__ float clip6(float v) { return fminf(fmaxf(v, 0.f), 6.f); }

// ---------------- prep ----------------
__global__ void prep_kernel(const float* __restrict__ g1, const float* __restrict__ b1,
                            const float* __restrict__ m1, const float* __restrict__ v1,
                            const float* __restrict__ g2, const float* __restrict__ b2,
                            const float* __restrict__ m2, const float* __restrict__ v2,
                            const float* __restrict__ g3, const float* __restrict__ b3,
                            const float* __restrict__ m3, const float* __restrict__ v3,
                            const float* __restrict__ we, const float* __restrict__ wpj)
{
    int t = threadIdx.x;
    if (t < C2) {
        float s = g1[t] * rsqrtf(v1[t] + EPSV);
        g_s1[t] = s; g_sh1[t] = b1[t] - m1[t] * s;
        float s2 = g2[t] * rsqrtf(v2[t] + EPSV);
        g_s2[t] = s2; g_sh2[t] = b2[t] - m2[t] * s2;
    }
    if (t < C1) {
        float s = g3[t] * rsqrtf(v3[t] + EPSV);
        g_s3[t] = s; g_sh3[t] = b3[t] - m3[t] * s;
    }
    for (int i = t; i < NB * C2; i += blockDim.x) g_ctxsum[i] = 0.f;
    for (int i = t; i < 384 * 32; i += blockDim.x) {
        float2 wv = *(const float2*)(we + (size_t)i * 2);
        hsplit2(wv.x, wv.y, g_weh[i], g_wel[i]);
    }
    for (int i = t; i < 64 * 192; i += blockDim.x) {
        float2 wv = *(const float2*)(wpj + (size_t)i * 2);
        g_wph[i] = hpack2(wv.x, wv.y);
    }
}

// ======================= EXPAND (unchanged from R6) =====================
__global__ void __launch_bounds__(256, 2) expand_kernel(const float* __restrict__ x)
{
    extern __shared__ uint32_t sm[];
    uint32_t* xsh = sm;                    // [128 px][XS]
    uint32_t* wsh = xsh + 128 * XS;        // [64 ch][XS] W hi
    uint32_t* wsl = wsh + 64 * XS;         // [64 ch][XS] W lo

    const int n    = blockIdx.y;
    const int pix0 = blockIdx.x * 128;
    const int tid  = threadIdx.x;
    const int wid  = tid >> 5;
    const int lane = tid & 31;
    const int g    = lane >> 2;
    const int tq   = lane & 3;
    const int wm   = wid & 1;
    const int wn   = wid >> 1;

    const uint32_t xshb = (uint32_t)__cvta_generic_to_shared(xsh);
    const uint32_t wshb = (uint32_t)__cvta_generic_to_shared(wsh);
    const uint32_t wslb = (uint32_t)__cvta_generic_to_shared(wsl);
    const int lrow = (lane & 7) + ((lane >> 3) & 1) * 8;
    const int loff = (lrow * XS + ((lane >> 4) * 4)) * 4;

    const float* xn = x + (size_t)n * C1 * HW;

    for (int idx = tid; idx < 128 * 32; idx += 256) {
        int j = idx >> 7, p = idx & 127;
        int pg = pix0 + p;
        float f0 = 0.f, f1 = 0.f;
        if (pg < HW) {
            f0 = xn[(size_t)(2 * j) * HW + pg];
            f1 = xn[(size_t)(2 * j + 1) * HW + pg];
        }
        xsh[p * XS + j] = hpack2(f0, f1);
    }

    for (int ct = 0; ct < 6; ++ct) {
        const int cbase = ct * 64;
        __syncthreads();
        for (int idx = tid; idx < 64 * 32; idx += 256) {
            int c = idx >> 5, j = idx & 31;
            wsh[c * XS + j] = g_weh[(cbase + c) * 32 + j];
            wsl[c * XS + j] = g_wel[(cbase + c) * 32 + j];
        }
        __syncthreads();

        float acc[2][4][4];
        #pragma unroll
        for (int mt = 0; mt < 2; ++mt)
            #pragma unroll
            for (int nt = 0; nt < 4; ++nt)
                #pragma unroll
                for (int i = 0; i < 4; ++i) acc[mt][nt][i] = 0.f;

        #pragma unroll
        for (int s = 0; s < 4; ++s) {
            const int soff = s * 32;
            uint32_t ah[2][4], al[2][4], bh[2][4];
            #pragma unroll
            for (int mt = 0; mt < 2; ++mt) {
                uint32_t off = (uint32_t)((wm * 32 + mt * 16) * XS * 4 + soff) + loff;
                ldsm4(ah[mt], wshb + off);
                ldsm4(al[mt], wslb + off);
            }
            #pragma unroll
            for (int q = 0; q < 2; ++q) {
                uint32_t off = (uint32_t)((wn * 32 + q * 16) * XS * 4 + soff) + loff;
                ldsm4(bh[q], xshb + off);
            }
            #pragma unroll
            for (int mt = 0; mt < 2; ++mt)
                #pragma unroll
                for (int q = 0; q < 2; ++q) {
                    mma16816(acc[mt][2*q],   ah[mt], bh[q][0], bh[q][2]);
                    mma16816(acc[mt][2*q],   al[mt], bh[q][0], bh[q][2]);
                    mma16816(acc[mt][2*q+1], ah[mt], bh[q][1], bh[q][3]);
                    mma16816(acc[mt][2*q+1], al[mt], bh[q][1], bh[q][3]);
                }
        }

        #pragma unroll
        for (int mt = 0; mt < 2; ++mt) {
            int c0 = cbase + wm * 32 + mt * 16 + g;
            int c8 = c0 + 8;
            float s0 = g_s1[c0], h0 = g_sh1[c0];
            float s8 = g_s1[c8], h8 = g_sh1[c8];
            __half* hp0 = g_hf + ((size_t)(n * C2 + c0)) * HW;
            __half* hp8 = g_hf + ((size_t)(n * C2 + c8)) * HW;
            float rs0 = 0.f, rs8 = 0.f;
            #pragma unroll
            for (int nt = 0; nt < 4; ++nt) {
                int p = pix0 + wn * 32 + nt * 8 + 2 * tq;
                float v00 = clip6(s0 * acc[mt][nt][0] + h0);
                float v01 = clip6(s0 * acc[mt][nt][1] + h0);
                float v10 = clip6(s8 * acc[mt][nt][2] + h8);
                float v11 = clip6(s8 * acc[mt][nt][3] + h8);
                if (p < HW) {
                    *(__half2*)(hp0 + p) = __floats2half2_rn(v00, v01);
                    *(__half2*)(hp8 + p) = __floats2half2_rn(v10, v11);
                    rs0 += v00 + v01; rs8 += v10 + v11;
                }
            }
            rs0 += __shfl_xor_sync(0xffffffffu, rs0, 1);
            rs0 += __shfl_xor_sync(0xffffffffu, rs0, 2);
            rs8 += __shfl_xor_sync(0xffffffffu, rs8, 1);
            rs8 += __shfl_xor_sync(0xffffffffu, rs8, 2);
            if (tq == 0) {
                atomicAdd(&g_ctxsum[n * C2 + c0], rs0);
                atomicAdd(&g_ctxsum[n * C2 + c8], rs8);
            }
        }
    }
}

// ---------------- context bias ----------------
__global__ void ctxbias_kernel(const float* __restrict__ wctx)
{
    __shared__ float cs[C2];
    const int n = blockIdx.x;
    const int o = threadIdx.x;
    cs[o] = g_ctxsum[n * C2 + o] * (1.f / (float)HW);
    __syncthreads();
    const float* wr = wctx + o * C2;
    float a = 0.f;
    #pragma unroll 4
    for (int c = 0; c < C2; ++c) a += cs[c] * wr[c];
    g_bias2[n * C2 + o] = g_s2[o] * a + g_sh2[o];
}

// ---------------- depthwise 3x3: sliding-window registers (6 LDS/output word) ----------------
__global__ void __launch_bounds__(224) dw_kernel(const float* __restrict__ wdw)
{
    __shared__ float sp0[HW];
    __shared__ float sp1[HW];
    __shared__ float wd[18];
    __shared__ float bs[2], sc[2];

    const int jw = blockIdx.x;         // channel-pair index 0..191
    const int n  = blockIdx.y;
    const int t  = threadIdx.x;
    const int c0 = 2 * jw;

    // load two fp16 planes, convert to fp32 in smem
    const uint4* src0 = (const uint4*)(g_hf + ((size_t)(n * C2 + c0)) * HW);
    const uint4* src1 = (const uint4*)(g_hf + ((size_t)(n * C2 + c0 + 1)) * HW);
    #pragma unroll
    for (int i = t; i < HW / 8; i += 224) {
        uint4 a = src0[i];
        uint4 b = src1[i];
        const __half2* ah = (const __half2*)&a;
        const __half2* bh = (const __half2*)&b;
        #pragma unroll
        for (int k = 0; k < 4; ++k) {
            float2 fa = __half22float2(ah[k]);
            float2 fb = __half22float2(bh[k]);
            sp0[8 * i + 2 * k]     = fa.x;
            sp0[8 * i + 2 * k + 1] = fa.y;
            sp1[8 * i + 2 * k]     = fb.x;
            sp1[8 * i + 2 * k + 1] = fb.y;
        }
    }
    if (t < 18) wd[t] = wdw[c0 * 9 + t];
    if (t < 2)  { bs[t] = g_bias2[n * C2 + c0 + t]; sc[t] = g_s2[c0 + t]; }
    __syncthreads();

    const int col  = t % HH;           // 0..55
    const int q    = t / HH;           // 0..3
    const int rbeg = q * 14;           // rows [rbeg, rbeg+14)
    const bool cl = (col > 0), cr = (col < HH - 1);
    uint32_t* op = g_h2 + ((size_t)(n * 192 + jw)) * HW;
    const float b0 = bs[0], b1 = bs[1], s0 = sc[0], s1 = sc[1];

    // register window: prev row (p*), current row (c*)
    float p0l, p0m, p0r, p1l, p1m, p1r;
    float c0l, c0m, c0r, c1l, c1m, c1r;

    if (rbeg > 0) {
        const float* r0p = sp0 + (rbeg - 1) * HH + col;
        const float* r1p = sp1 + (rbeg - 1) * HH + col;
        p0l = cl ? r0p[-1] : 0.f; p0m = r0p[0]; p0r = cr ? r0p[1] : 0.f;
        p1l = cl ? r1p[-1] : 0.f; p1m = r1p[0]; p1r = cr ? r1p[1] : 0.f;
    } else {
        p0l = p0m = p0r = p1l = p1m = p1r = 0.f;
    }
    {
        const float* r0c = sp0 + rbeg * HH + col;
        const float* r1c = sp1 + rbeg * HH + col;
        c0l = cl ? r0c[-1] : 0.f; c0m = r0c[0]; c0r = cr ? r0c[1] : 0.f;
        c1l = cl ? r1c[-1] : 0.f; c1m = r1c[0]; c1r = cr ? r1c[1] : 0.f;
    }

    #pragma unroll
    for (int j = 0; j < 14; ++j) {
        const int r  = rbeg + j;
        const int nr = r + 1;
        float n0l, n0m, n0r, n1l, n1m, n1r;
        if (nr < HH) {
            const float* r0n = sp0 + nr * HH + col;
            const float* r1n = sp1 + nr * HH + col;
            n0l = cl ? r0n[-1] : 0.f; n0m = r0n[0]; n0r = cr ? r0n[1] : 0.f;
            n1l = cl ? r1n[-1] : 0.f; n1m = r1n[0]; n1r = cr ? r1n[1] : 0.f;
        } else {
            n0l = n0m = n0r = n1l = n1m = n1r = 0.f;
        }
        float a0 = p0l * wd[0] + p0m * wd[1] + p0r * wd[2]
                 + c0l * wd[3] + c0m * wd[4] + c0r * wd[5]
                 + n0l * wd[6] + n0m * wd[7] + n0r * wd[8];
        float a1 = p1l * wd[9]  + p1m * wd[10] + p1r * wd[11]
                 + c1l * wd[12] + c1m * wd[13] + c1r * wd[14]
                 + n1l * wd[15] + n1m * wd[16] + n1r * wd[17];
        float v0 = clip6(s0 * a0 + b0);
        float v1 = clip6(s1 * a1 + b1);
        op[r * HH + col] = hpack2(v0, v1);
        p0l = c0l; p0m = c0m; p0r = c0r;
        p1l = c1l; p1m = c1m; p1r = c1r;
        c0l = n0l; c0m = n0m; c0r = n0r;
        c1l = n1l; c1m = n1m; c1r = n1r;
    }
}

// ======================= PROJECT (single-term fp16) =====================
__global__ void __launch_bounds__(256, 2) project_kernel(const float* __restrict__ x,
                                                         float* __restrict__ out)
{
    extern __shared__ uint32_t sm[];
    uint32_t* xsh = sm;                    // [128 px][XS]
    uint32_t* wsh = xsh + 128 * XS;        // [64 ch][XS]

    const int n    = blockIdx.y;
    const int pix0 = blockIdx.x * 128;
    const int tid  = threadIdx.x;
    const int wid  = tid >> 5;
    const int lane = tid & 31;
    const int g    = lane >> 2;
    const int tq   = lane & 3;
    const int wm   = wid & 1;
    const int wn   = wid >> 1;

    const uint32_t xshb = (uint32_t)__cvta_generic_to_shared(xsh);
    const uint32_t wshb = (uint32_t)__cvta_generic_to_shared(wsh);
    const int lrow = (lane & 7) + ((lane >> 3) & 1) * 8;
    const int loff = (lrow * XS + ((lane >> 4) * 4)) * 4;

    float acc[2][4][4];
    #pragma unroll
    for (int mt = 0; mt < 2; ++mt)
        #pragma unroll
        for (int nt = 0; nt < 4; ++nt)
            #pragma unroll
            for (int i = 0; i < 4; ++i) acc[mt][nt][i] = 0.f;

    for (int kt = 0; kt < 6; ++kt) {
        __syncthreads();
        const uint32_t* hb = g_h2 + ((size_t)(n * 192 + kt * 32)) * HW;
        for (int idx = tid; idx < 128 * 32; idx += 256) {
            int j = idx >> 7, p = idx & 127;
            int pg = pix0 + p;
            xsh[p * XS + j] = (pg < HW) ? hb[(size_t)j * HW + pg] : 0u;
        }
        for (int idx = tid; idx < 64 * 32; idx += 256) {
            int c = idx >> 5, j = idx & 31;
            wsh[c * XS + j] = g_wph[c * 192 + kt * 32 + j];
        }
        __syncthreads();

        #pragma unroll
        for (int s = 0; s < 4; ++s) {
            const int soff = s * 32;
            uint32_t ah[2][4], bh[2][4];
            #pragma unroll
            for (int mt = 0; mt < 2; ++mt) {
                uint32_t off = (uint32_t)((wm * 32 + mt * 16) * XS * 4 + soff) + loff;
                ldsm4(ah[mt], wshb + off);
            }
            #pragma unroll
            for (int q = 0; q < 2; ++q) {
                uint32_t off = (uint32_t)((wn * 32 + q * 16) * XS * 4 + soff) + loff;
                ldsm4(bh[q], xshb + off);
            }
            #pragma unroll
            for (int mt = 0; mt < 2; ++mt)
                #pragma unroll
                for (int q = 0; q < 2; ++q) {
                    mma16816(acc[mt][2*q],   ah[mt], bh[q][0], bh[q][2]);
                    mma16816(acc[mt][2*q+1], ah[mt], bh[q][1], bh[q][3]);
                }
        }
    }

    // epilogue: BN3 + residual
    #pragma unroll
    for (int mt = 0; mt < 2; ++mt) {
        int c0 = wm * 32 + mt * 16 + g;
        int c8 = c0 + 8;
        float s0 = g_s3[c0], h0 = g_sh3[c0];
        float s8 = g_s3[c8], h8 = g_sh3[c8];
        const float* xp0 = x   + ((size_t)(n * C1 + c0)) * HW;
        const float* xp8 = x   + ((size_t)(n * C1 + c8)) * HW;
        float*       op0 = out + ((size_t)(n * C1 + c0)) * HW;
        float*       op8 = out + ((size_t)(n * C1 + c8)) * HW;
        #pragma unroll
        for (int nt = 0; nt < 4; ++nt) {
            int p = pix0 + wn * 32 + nt * 8 + 2 * tq;
            if (p < HW) {
                float2 r0 = *(const float2*)(xp0 + p);
                float2 r8 = *(const float2*)(xp8 + p);
                *(float2*)(op0 + p) = make_float2(s0 * acc[mt][nt][0] + h0 + r0.x,
                                                  s0 * acc[mt][nt][1] + h0 + r0.y);
                *(float2*)(op8 + p) = make_float2(s8 * acc[mt][nt][2] + h8 + r8.x,
                                                  s8 * acc[mt][nt][3] + h8 + r8.y);
            }
        }
    }
}

// ---------------- launch ----------------
extern "C" void kernel_launch(void* const* d_in, const int* in_sizes, int n_in,
                              void* d_out, int out_size)
{
    const float* x        = (const float*)d_in[0];
    const float* w_expand = (const float*)d_in[1];
    const float* g1 = (const float*)d_in[2];
    const float* b1 = (const float*)d_in[3];
    const float* m1 = (const float*)d_in[4];
    const float* v1 = (const float*)d_in[5];
    const float* w_dw  = (const float*)d_in[6];
    const float* w_ctx = (const float*)d_in[7];
    const float* g2 = (const float*)d_in[8];
    const float* b2 = (const float*)d_in[9];
    const float* m2 = (const float*)d_in[10];
    const float* v2 = (const float*)d_in[11];
    const float* w_proj = (const float*)d_in[12];
    const float* g3 = (const float*)d_in[13];
    const float* b3 = (const float*)d_in[14];
    const float* m3 = (const float*)d_in[15];
    const float* v3 = (const float*)d_in[16];
    float* out = (float*)d_out;

    const int smem_expand  = (128 * XS + 2 * 64 * XS) * (int)sizeof(uint32_t); // 36864
    const int smem_project = (128 * XS + 64 * XS) * (int)sizeof(uint32_t);     // 27648
    cudaFuncSetAttribute((const void*)expand_kernel,
                         cudaFuncAttributeMaxDynamicSharedMemorySize, smem_expand);
    cudaFuncSetAttribute((const void*)project_kernel,
                         cudaFuncAttributeMaxDynamicSharedMemorySize, smem_project);

    prep_kernel<<<1, 512>>>(g1, b1, m1, v1, g2, b2, m2, v2, g3, b3, m3, v3,
                            w_expand, w_proj);
    expand_kernel<<<dim3(25, NB), 256, smem_expand>>>(x);
    ctxbias_kernel<<<NB, C2>>>(w_ctx);
    dw_kernel<<<dim3(192, NB), 224>>>(w_dw);
    project_kernel<<<dim3(25, NB), 256, smem_project>>>(x, out);
}

// round 8
// speedup vs baseline: 2.7265x; 1.1093x over previous
#include <cuda_runtime.h>
#include <cuda_fp16.h>
#include <cstdint>

#define NB  32
#define C1  64
#define C2  384
#define HH  56
#define HW  3136
#define EPSV 1e-5f
#define XS  36            // smem row stride in 32-bit words (conflict-free for ldmatrix)

// ---------------- scratch (device globals; no allocation allowed) ----------------
__device__ __half   g_hf  [(size_t)NB * C2 * HW];     // expand output fp16 planes (dw input)
__device__ uint32_t g_h2  [(size_t)NB * 192 * HW];    // dw output, packed fp16 ch-pair words
__device__ uint32_t g_weh [384 * 32];                  // w_expand fp16-pair words [c][j]
__device__ uint32_t g_wph [64 * 192];                  // w_proj   fp16-pair words [c][j]
__device__ float g_ctxsum[NB * C2];
__device__ float g_bias2 [NB * C2];
__device__ float g_s1[C2], g_sh1[C2];
__device__ float g_s2[C2], g_sh2[C2];
__device__ float g_s3[C1], g_sh3[C1];

// ---------------- helpers ----------------
__device__ __forceinline__ uint32_t hpack2(float f0, float f1) {
    __half2 H = __floats2half2_rn(f0, f1);
    return *reinterpret_cast<uint32_t*>(&H);
}

__device__ __forceinline__ void mma16816(float* c, const uint32_t* a, uint32_t b0, uint32_t b1) {
    asm volatile(
        "mma.sync.aligned.m16n8k16.row.col.f32.f16.f16.f32 "
        "{%0,%1,%2,%3},{%4,%5,%6,%7},{%8,%9},{%0,%1,%2,%3};"
        : "+f"(c[0]), "+f"(c[1]), "+f"(c[2]), "+f"(c[3])
        : "r"(a[0]), "r"(a[1]), "r"(a[2]), "r"(a[3]), "r"(b0), "r"(b1));
}

__device__ __forceinline__ void ldsm4(uint32_t* r, uint32_t addr) {
    asm volatile("ldmatrix.sync.aligned.m8n8.x4.shared.b16 {%0,%1,%2,%3},[%4];"
                 : "=r"(r[0]), "=r"(r[1]), "=r"(r[2]), "=r"(r[3]) : "r"(addr));
}

__device__ __forceinline__ float clip6(float v) { return fminf(fmaxf(v, 0.f), 6.f); }

// ---------------- prep ----------------
__global__ void prep_kernel(const float* __restrict__ g1, const float* __restrict__ b1,
                            const float* __restrict__ m1, const float* __restrict__ v1,
                            const float* __restrict__ g2, const float* __restrict__ b2,
                            const float* __restrict__ m2, const float* __restrict__ v2,
                            const float* __restrict__ g3, const float* __restrict__ b3,
                            const float* __restrict__ m3, const float* __restrict__ v3,
                            const float* __restrict__ we, const float* __restrict__ wpj)
{
    int t = threadIdx.x;
    if (t < C2) {
        float s = g1[t] * rsqrtf(v1[t] + EPSV);
        g_s1[t] = s; g_sh1[t] = b1[t] - m1[t] * s;
        float s2 = g2[t] * rsqrtf(v2[t] + EPSV);
        g_s2[t] = s2; g_sh2[t] = b2[t] - m2[t] * s2;
    }
    if (t < C1) {
        float s = g3[t] * rsqrtf(v3[t] + EPSV);
        g_s3[t] = s; g_sh3[t] = b3[t] - m3[t] * s;
    }
    for (int i = t; i < NB * C2; i += blockDim.x) g_ctxsum[i] = 0.f;
    for (int i = t; i < 384 * 32; i += blockDim.x) {
        float2 wv = *(const float2*)(we + (size_t)i * 2);
        g_weh[i] = hpack2(wv.x, wv.y);
    }
    for (int i = t; i < 64 * 192; i += blockDim.x) {
        float2 wv = *(const float2*)(wpj + (size_t)i * 2);
        g_wph[i] = hpack2(wv.x, wv.y);
    }
}

// ======================= EXPAND (single-term fp16) =====================
__global__ void __launch_bounds__(256, 2) expand_kernel(const float* __restrict__ x)
{
    extern __shared__ uint32_t sm[];
    uint32_t* xsh = sm;                    // [128 px][XS]
    uint32_t* wsh = xsh + 128 * XS;        // [64 ch][XS]

    const int n    = blockIdx.y;
    const int pix0 = blockIdx.x * 128;
    const int tid  = threadIdx.x;
    const int wid  = tid >> 5;
    const int lane = tid & 31;
    const int g    = lane >> 2;
    const int tq   = lane & 3;
    const int wm   = wid & 1;
    const int wn   = wid >> 1;

    const uint32_t xshb = (uint32_t)__cvta_generic_to_shared(xsh);
    const uint32_t wshb = (uint32_t)__cvta_generic_to_shared(wsh);
    const int lrow = (lane & 7) + ((lane >> 3) & 1) * 8;
    const int loff = (lrow * XS + ((lane >> 4) * 4)) * 4;

    const float* xn = x + (size_t)n * C1 * HW;

    for (int idx = tid; idx < 128 * 32; idx += 256) {
        int j = idx >> 7, p = idx & 127;
        int pg = pix0 + p;
        float f0 = 0.f, f1 = 0.f;
        if (pg < HW) {
            f0 = xn[(size_t)(2 * j) * HW + pg];
            f1 = xn[(size_t)(2 * j + 1) * HW + pg];
        }
        xsh[p * XS + j] = hpack2(f0, f1);
    }

    for (int ct = 0; ct < 6; ++ct) {
        const int cbase = ct * 64;
        __syncthreads();
        for (int idx = tid; idx < 64 * 32; idx += 256) {
            int c = idx >> 5, j = idx & 31;
            wsh[c * XS + j] = g_weh[(cbase + c) * 32 + j];
        }
        __syncthreads();

        float acc[2][4][4];
        #pragma unroll
        for (int mt = 0; mt < 2; ++mt)
            #pragma unroll
            for (int nt = 0; nt < 4; ++nt)
                #pragma unroll
                for (int i = 0; i < 4; ++i) acc[mt][nt][i] = 0.f;

        #pragma unroll
        for (int s = 0; s < 4; ++s) {
            const int soff = s * 32;
            uint32_t ah[2][4], bh[2][4];
            #pragma unroll
            for (int mt = 0; mt < 2; ++mt) {
                uint32_t off = (uint32_t)((wm * 32 + mt * 16) * XS * 4 + soff) + loff;
                ldsm4(ah[mt], wshb + off);
            }
            #pragma unroll
            for (int q = 0; q < 2; ++q) {
                uint32_t off = (uint32_t)((wn * 32 + q * 16) * XS * 4 + soff) + loff;
                ldsm4(bh[q], xshb + off);
            }
            #pragma unroll
            for (int mt = 0; mt < 2; ++mt)
                #pragma unroll
                for (int q = 0; q < 2; ++q) {
                    mma16816(acc[mt][2*q],   ah[mt], bh[q][0], bh[q][2]);
                    mma16816(acc[mt][2*q+1], ah[mt], bh[q][1], bh[q][3]);
                }
        }

        #pragma unroll
        for (int mt = 0; mt < 2; ++mt) {
            int c0 = cbase + wm * 32 + mt * 16 + g;
            int c8 = c0 + 8;
            float s0 = g_s1[c0], h0 = g_sh1[c0];
            float s8 = g_s1[c8], h8 = g_sh1[c8];
            __half* hp0 = g_hf + ((size_t)(n * C2 + c0)) * HW;
            __half* hp8 = g_hf + ((size_t)(n * C2 + c8)) * HW;
            float rs0 = 0.f, rs8 = 0.f;
            #pragma unroll
            for (int nt = 0; nt < 4; ++nt) {
                int p = pix0 + wn * 32 + nt * 8 + 2 * tq;
                float v00 = clip6(s0 * acc[mt][nt][0] + h0);
                float v01 = clip6(s0 * acc[mt][nt][1] + h0);
                float v10 = clip6(s8 * acc[mt][nt][2] + h8);
                float v11 = clip6(s8 * acc[mt][nt][3] + h8);
                if (p < HW) {
                    *(__half2*)(hp0 + p) = __floats2half2_rn(v00, v01);
                    *(__half2*)(hp8 + p) = __floats2half2_rn(v10, v11);
                    rs0 += v00 + v01; rs8 += v10 + v11;
                }
            }
            rs0 += __shfl_xor_sync(0xffffffffu, rs0, 1);
            rs0 += __shfl_xor_sync(0xffffffffu, rs0, 2);
            rs8 += __shfl_xor_sync(0xffffffffu, rs8, 1);
            rs8 += __shfl_xor_sync(0xffffffffu, rs8, 2);
            if (tq == 0) {
                atomicAdd(&g_ctxsum[n * C2 + c0], rs0);
                atomicAdd(&g_ctxsum[n * C2 + c8], rs8);
            }
        }
    }
}

// ---------------- context bias ----------------
__global__ void ctxbias_kernel(const float* __restrict__ wctx)
{
    __shared__ float cs[C2];
    const int n = blockIdx.x;
    const int o = threadIdx.x;
    cs[o] = g_ctxsum[n * C2 + o] * (1.f / (float)HW);
    __syncthreads();
    const float* wr = wctx + o * C2;
    float a = 0.f;
    #pragma unroll 4
    for (int c = 0; c < C2; ++c) a += cs[c] * wr[c];
    g_bias2[n * C2 + o] = g_s2[o] * a + g_sh2[o];
}

// ---------------- depthwise 3x3: packed-half2 smem + sliding window ----------------
__global__ void __launch_bounds__(224) dw_kernel(const float* __restrict__ wdw)
{
    __shared__ uint32_t sp[HW];        // word p = (ch0[p], ch1[p]) fp16 pair
    __shared__ float wd[18];
    __shared__ float bs[2], sc[2];

    const int jw = blockIdx.x;         // channel-pair index 0..191
    const int n  = blockIdx.y;
    const int t  = threadIdx.x;
    const int c0 = 2 * jw;

    // load two fp16 planes, interleave-pack into smem (no float conversion)
    const uint4* src0 = (const uint4*)(g_hf + ((size_t)(n * C2 + c0)) * HW);
    const uint4* src1 = (const uint4*)(g_hf + ((size_t)(n * C2 + c0 + 1)) * HW);
    #pragma unroll
    for (int i = t; i < HW / 8; i += 224) {
        uint4 a = src0[i];
        uint4 b = src1[i];
        const uint32_t* aw = (const uint32_t*)&a;
        const uint32_t* bw = (const uint32_t*)&b;
        #pragma unroll
        for (int k = 0; k < 4; ++k) {
            sp[8 * i + 2 * k]     = __byte_perm(aw[k], bw[k], 0x5410);
            sp[8 * i + 2 * k + 1] = __byte_perm(aw[k], bw[k], 0x7632);
        }
    }
    if (t < 18) wd[t] = wdw[c0 * 9 + t];
    if (t < 2)  { bs[t] = g_bias2[n * C2 + c0 + t]; sc[t] = g_s2[c0 + t]; }
    __syncthreads();

    const int col  = t % HH;           // 0..55
    const int q    = t / HH;           // 0..3
    const int rbeg = q * 14;
    const bool cl = (col > 0), cr = (col < HH - 1);
    uint32_t* op = g_h2 + ((size_t)(n * 192 + jw)) * HW;
    const float b0 = bs[0], b1 = bs[1], s0 = sc[0], s1 = sc[1];

    // window registers as float2 (x=ch0, y=ch1)
    float2 pl, pm, pr, cl2, cm, cr2;
    const float2 z2 = make_float2(0.f, 0.f);

    if (rbeg > 0) {
        const uint32_t* rp = sp + (rbeg - 1) * HH + col;
        pl = cl ? __half22float2(*(const __half2*)&rp[-1]) : z2;
        pm = __half22float2(*(const __half2*)&rp[0]);
        pr = cr ? __half22float2(*(const __half2*)&rp[1]) : z2;
    } else { pl = pm = pr = z2; }
    {
        const uint32_t* rc = sp + rbeg * HH + col;
        cl2 = cl ? __half22float2(*(const __half2*)&rc[-1]) : z2;
        cm  = __half22float2(*(const __half2*)&rc[0]);
        cr2 = cr ? __half22float2(*(const __half2*)&rc[1]) : z2;
    }

    #pragma unroll
    for (int j = 0; j < 14; ++j) {
        const int r  = rbeg + j;
        const int nr = r + 1;
        float2 nl, nm, nr2;
        if (nr < HH) {
            const uint32_t* rn = sp + nr * HH + col;
            nl  = cl ? __half22float2(*(const __half2*)&rn[-1]) : z2;
            nm  = __half22float2(*(const __half2*)&rn[0]);
            nr2 = cr ? __half22float2(*(const __half2*)&rn[1]) : z2;
        } else { nl = nm = nr2 = z2; }
        float a0 = pl.x * wd[0] + pm.x * wd[1] + pr.x * wd[2]
                 + cl2.x * wd[3] + cm.x * wd[4] + cr2.x * wd[5]
                 + nl.x * wd[6] + nm.x * wd[7] + nr2.x * wd[8];
        float a1 = pl.y * wd[9]  + pm.y * wd[10] + pr.y * wd[11]
                 + cl2.y * wd[12] + cm.y * wd[13] + cr2.y * wd[14]
                 + nl.y * wd[15] + nm.y * wd[16] + nr2.y * wd[17];
        float v0 = clip6(s0 * a0 + b0);
        float v1 = clip6(s1 * a1 + b1);
        op[r * HH + col] = hpack2(v0, v1);
        pl = cl2; pm = cm; pr = cr2;
        cl2 = nl; cm = nm; cr2 = nr2;
    }
}

// ======================= PROJECT (single-term fp16) =====================
__global__ void __launch_bounds__(256, 2) project_kernel(const float* __restrict__ x,
                                                         float* __restrict__ out)
{
    extern __shared__ uint32_t sm[];
    uint32_t* xsh = sm;                    // [128 px][XS]
    uint32_t* wsh = xsh + 128 * XS;        // [64 ch][XS]

    const int n    = blockIdx.y;
    const int pix0 = blockIdx.x * 128;
    const int tid  = threadIdx.x;
    const int wid  = tid >> 5;
    const int lane = tid & 31;
    const int g    = lane >> 2;
    const int tq   = lane & 3;
    const int wm   = wid & 1;
    const int wn   = wid >> 1;

    const uint32_t xshb = (uint32_t)__cvta_generic_to_shared(xsh);
    const uint32_t wshb = (uint32_t)__cvta_generic_to_shared(wsh);
    const int lrow = (lane & 7) + ((lane >> 3) & 1) * 8;
    const int loff = (lrow * XS + ((lane >> 4) * 4)) * 4;

    float acc[2][4][4];
    #pragma unroll
    for (int mt = 0; mt < 2; ++mt)
        #pragma unroll
        for (int nt = 0; nt < 4; ++nt)
            #pragma unroll
            for (int i = 0; i < 4; ++i) acc[mt][nt][i] = 0.f;

    for (int kt = 0; kt < 6; ++kt) {
        __syncthreads();
        const uint32_t* hb = g_h2 + ((size_t)(n * 192 + kt * 32)) * HW;
        for (int idx = tid; idx < 128 * 32; idx += 256) {
            int j = idx >> 7, p = idx & 127;
            int pg = pix0 + p;
            xsh[p * XS + j] = (pg < HW) ? hb[(size_t)j * HW + pg] : 0u;
        }
        for (int idx = tid; idx < 64 * 32; idx += 256) {
            int c = idx >> 5, j = idx & 31;
            wsh[c * XS + j] = g_wph[c * 192 + kt * 32 + j];
        }
        __syncthreads();

        #pragma unroll
        for (int s = 0; s < 4; ++s) {
            const int soff = s * 32;
            uint32_t ah[2][4], bh[2][4];
            #pragma unroll
            for (int mt = 0; mt < 2; ++mt) {
                uint32_t off = (uint32_t)((wm * 32 + mt * 16) * XS * 4 + soff) + loff;
                ldsm4(ah[mt], wshb + off);
            }
            #pragma unroll
            for (int q = 0; q < 2; ++q) {
                uint32_t off = (uint32_t)((wn * 32 + q * 16) * XS * 4 + soff) + loff;
                ldsm4(bh[q], xshb + off);
            }
            #pragma unroll
            for (int mt = 0; mt < 2; ++mt)
                #pragma unroll
                for (int q = 0; q < 2; ++q) {
                    mma16816(acc[mt][2*q],   ah[mt], bh[q][0], bh[q][2]);
                    mma16816(acc[mt][2*q+1], ah[mt], bh[q][1], bh[q][3]);
                }
        }
    }

    // epilogue: BN3 + residual
    #pragma unroll
    for (int mt = 0; mt < 2; ++mt) {
        int c0 = wm * 32 + mt * 16 + g;
        int c8 = c0 + 8;
        float s0 = g_s3[c0], h0 = g_sh3[c0];
        float s8 = g_s3[c8], h8 = g_sh3[c8];
        const float* xp0 = x   + ((size_t)(n * C1 + c0)) * HW;
        const float* xp8 = x   + ((size_t)(n * C1 + c8)) * HW;
        float*       op0 = out + ((size_t)(n * C1 + c0)) * HW;
        float*       op8 = out + ((size_t)(n * C1 + c8)) * HW;
        #pragma unroll
        for (int nt = 0; nt < 4; ++nt) {
            int p = pix0 + wn * 32 + nt * 8 + 2 * tq;
            if (p < HW) {
                float2 r0 = *(const float2*)(xp0 + p);
                float2 r8 = *(const float2*)(xp8 + p);
                *(float2*)(op0 + p) = make_float2(s0 * acc[mt][nt][0] + h0 + r0.x,
                                                  s0 * acc[mt][nt][1] + h0 + r0.y);
                *(float2*)(op8 + p) = make_float2(s8 * acc[mt][nt][2] + h8 + r8.x,
                                                  s8 * acc[mt][nt][3] + h8 + r8.y);
            }
        }
    }
}

// ---------------- launch ----------------
extern "C" void kernel_launch(void* const* d_in, const int* in_sizes, int n_in,
                              void* d_out, int out_size)
{
    const float* x        = (const float*)d_in[0];
    const float* w_expand = (const float*)d_in[1];
    const float* g1 = (const float*)d_in[2];
    const float* b1 = (const float*)d_in[3];
    const float* m1 = (const float*)d_in[4];
    const float* v1 = (const float*)d_in[5];
    const float* w_dw  = (const float*)d_in[6];
    const float* w_ctx = (const float*)d_in[7];
    const float* g2 = (const float*)d_in[8];
    const float* b2 = (const float*)d_in[9];
    const float* m2 = (const float*)d_in[10];
    const float* v2 = (const float*)d_in[11];
    const float* w_proj = (const float*)d_in[12];
    const float* g3 = (const float*)d_in[13];
    const float* b3 = (const float*)d_in[14];
    const float* m3 = (const float*)d_in[15];
    const float* v3 = (const float*)d_in[16];
    float* out = (float*)d_out;

    const int smem_gemm = (128 * XS + 64 * XS) * (int)sizeof(uint32_t); // 27648
    cudaFuncSetAttribute((const void*)expand_kernel,
                         cudaFuncAttributeMaxDynamicSharedMemorySize, smem_gemm);
    cudaFuncSetAttribute((const void*)project_kernel,
                         cudaFuncAttributeMaxDynamicSharedMemorySize, smem_gemm);

    prep_kernel<<<1, 512>>>(g1, b1, m1, v1, g2, b2, m2, v2, g3, b3, m3, v3,
                            w_expand, w_proj);
    expand_kernel<<<dim3(25, NB), 256, smem_gemm>>>(x);
    ctxbias_kernel<<<NB, C2>>>(w_ctx);
    dw_kernel<<<dim3(192, NB), 224>>>(w_dw);
    project_kernel<<<dim3(25, NB), 256, smem_gemm>>>(x, out);
}

// round 10
// speedup vs baseline: 3.1344x; 1.1496x over previous
#include <cuda_runtime.h>
#include <cuda_fp16.h>
#include <cstdint>

#define NB  32
#define C1  64
#define C2  384
#define HH  56
#define HW  3136
#define EPSV 1e-5f
#define XS  36            // smem row stride in 32-bit words (conflict-free for ldmatrix)

// ---------------- scratch (device globals; no allocation allowed) ----------------
__device__ __half   g_hf  [(size_t)NB * C2 * HW];     // expand output fp16 planes (dw input)
__device__ uint32_t g_h2  [(size_t)NB * 192 * HW];    // dw output, packed fp16 ch-pair words
__device__ uint32_t g_weh [384 * 32];                  // w_expand fp16-pair words [c][j]
__device__ uint32_t g_wph [64 * 192];                  // w_proj   fp16-pair words [c][j]
__device__ float g_ctxsum[NB * C2];
__device__ float g_bias2 [NB * C2];
__device__ float g_s1[C2], g_sh1[C2];
__device__ float g_s2[C2], g_sh2[C2];
__device__ float g_s3[C1], g_sh3[C1];

// ---------------- helpers ----------------
__device__ __forceinline__ uint32_t hpack2(float f0, float f1) {
    __half2 H = __floats2half2_rn(f0, f1);
    return *reinterpret_cast<uint32_t*>(&H);
}

__device__ __forceinline__ void mma16816(float* c, const uint32_t* a, uint32_t b0, uint32_t b1) {
    asm volatile(
        "mma.sync.aligned.m16n8k16.row.col.f32.f16.f16.f32 "
        "{%0,%1,%2,%3},{%4,%5,%6,%7},{%8,%9},{%0,%1,%2,%3};"
        : "+f"(c[0]), "+f"(c[1]), "+f"(c[2]), "+f"(c[3])
        : "r"(a[0]), "r"(a[1]), "r"(a[2]), "r"(a[3]), "r"(b0), "r"(b1));
}

__device__ __forceinline__ void ldsm4(uint32_t* r, uint32_t addr) {
    asm volatile("ldmatrix.sync.aligned.m8n8.x4.shared.b16 {%0,%1,%2,%3},[%4];"
                 : "=r"(r[0]), "=r"(r[1]), "=r"(r[2]), "=r"(r[3]) : "r"(addr));
}

__device__ __forceinline__ void cpasync4(uint32_t dst, const void* src, bool valid) {
    asm volatile("cp.async.ca.shared.global [%0], [%1], 4, %2;"
                 :: "r"(dst), "l"(src), "r"(valid ? 4 : 0) : "memory");
}
__device__ __forceinline__ void cpasync_commit() {
    asm volatile("cp.async.commit_group;" ::: "memory");
}

__device__ __forceinline__ float clip6(float v) { return fminf(fmaxf(v, 0.f), 6.f); }

// ---------------- prep ----------------
__global__ void prep_kernel(const float* __restrict__ g1, const float* __restrict__ b1,
                            const float* __restrict__ m1, const float* __restrict__ v1,
                            const float* __restrict__ g2, const float* __restrict__ b2,
                            const float* __restrict__ m2, const float* __restrict__ v2,
                            const float* __restrict__ g3, const float* __restrict__ b3,
                            const float* __restrict__ m3, const float* __restrict__ v3,
                            const float* __restrict__ we, const float* __restrict__ wpj)
{
    int t = threadIdx.x;
    if (t < C2) {
        float s = g1[t] * rsqrtf(v1[t] + EPSV);
        g_s1[t] = s; g_sh1[t] = b1[t] - m1[t] * s;
        float s2 = g2[t] * rsqrtf(v2[t] + EPSV);
        g_s2[t] = s2; g_sh2[t] = b2[t] - m2[t] * s2;
    }
    if (t < C1) {
        float s = g3[t] * rsqrtf(v3[t] + EPSV);
        g_s3[t] = s; g_sh3[t] = b3[t] - m3[t] * s;
    }
    for (int i = t; i < NB * C2; i += blockDim.x) g_ctxsum[i] = 0.f;
    for (int i = t; i < 384 * 32; i += blockDim.x) {
        float2 wv = *(const float2*)(we + (size_t)i * 2);
        g_weh[i] = hpack2(wv.x, wv.y);
    }
    for (int i = t; i < 64 * 192; i += blockDim.x) {
        float2 wv = *(const float2*)(wpj + (size_t)i * 2);
        g_wph[i] = hpack2(wv.x, wv.y);
    }
}

// ======================= EXPAND: resident full-W, no intra-loop syncs =====================
__global__ void __launch_bounds__(256, 2) expand_kernel(const float* __restrict__ x)
{
    extern __shared__ uint32_t sm[];
    uint32_t* xsh = sm;                    // [128 px][XS]
    uint32_t* wsh = xsh + 128 * XS;        // [384 ch][XS] full W

    const int n    = blockIdx.y;
    const int pix0 = blockIdx.x * 128;
    const int tid  = threadIdx.x;
    const int wid  = tid >> 5;
    const int lane = tid & 31;
    const int g    = lane >> 2;
    const int tq   = lane & 3;
    const int wm   = wid & 1;
    const int wn   = wid >> 1;

    const uint32_t xshb = (uint32_t)__cvta_generic_to_shared(xsh);
    const uint32_t wshb = (uint32_t)__cvta_generic_to_shared(wsh);
    const int lrow = (lane & 7) + ((lane >> 3) & 1) * 8;
    const int loff = (lrow * XS + ((lane >> 4) * 4)) * 4;

    const float* xn = x + (size_t)n * C1 * HW;

    // X tile
    for (int idx = tid; idx < 128 * 32; idx += 256) {
        int j = idx >> 7, p = idx & 127;
        int pg = pix0 + p;
        float f0 = 0.f, f1 = 0.f;
        if (pg < HW) {
            f0 = xn[(size_t)(2 * j) * HW + pg];
            f1 = xn[(size_t)(2 * j + 1) * HW + pg];
        }
        xsh[p * XS + j] = hpack2(f0, f1);
    }
    // full W (uint4 loads; c*XS stays 16B-aligned since XS*4=144 ≡ 0 mod 16)
    {
        const uint4* src = (const uint4*)g_weh;
        for (int i = tid; i < 3072; i += 256) {
            int c = i >> 3, jq = (i & 7) * 4;
            *(uint4*)&wsh[c * XS + jq] = src[i];
        }
    }
    __syncthreads();

    for (int ct = 0; ct < 6; ++ct) {
        const int cbase = ct * 64;

        float acc[2][4][4];
        #pragma unroll
        for (int mt = 0; mt < 2; ++mt)
            #pragma unroll
            for (int nt = 0; nt < 4; ++nt)
                #pragma unroll
                for (int i = 0; i < 4; ++i) acc[mt][nt][i] = 0.f;

        #pragma unroll
        for (int s = 0; s < 4; ++s) {
            const int soff = s * 32;
            uint32_t ah[2][4], bh[2][4];
            #pragma unroll
            for (int mt = 0; mt < 2; ++mt) {
                uint32_t off = (uint32_t)((cbase + wm * 32 + mt * 16) * XS * 4 + soff) + loff;
                ldsm4(ah[mt], wshb + off);
            }
            #pragma unroll
            for (int q = 0; q < 2; ++q) {
                uint32_t off = (uint32_t)((wn * 32 + q * 16) * XS * 4 + soff) + loff;
                ldsm4(bh[q], xshb + off);
            }
            #pragma unroll
            for (int mt = 0; mt < 2; ++mt)
                #pragma unroll
                for (int q = 0; q < 2; ++q) {
                    mma16816(acc[mt][2*q],   ah[mt], bh[q][0], bh[q][2]);
                    mma16816(acc[mt][2*q+1], ah[mt], bh[q][1], bh[q][3]);
                }
        }

        #pragma unroll
        for (int mt = 0; mt < 2; ++mt) {
            int c0 = cbase + wm * 32 + mt * 16 + g;
            int c8 = c0 + 8;
            float s0 = g_s1[c0], h0 = g_sh1[c0];
            float s8 = g_s1[c8], h8 = g_sh1[c8];
            __half* hp0 = g_hf + ((size_t)(n * C2 + c0)) * HW;
            __half* hp8 = g_hf + ((size_t)(n * C2 + c8)) * HW;
            float rs0 = 0.f, rs8 = 0.f;
            #pragma unroll
            for (int nt = 0; nt < 4; ++nt) {
                int p = pix0 + wn * 32 + nt * 8 + 2 * tq;
                float v00 = clip6(s0 * acc[mt][nt][0] + h0);
                float v01 = clip6(s0 * acc[mt][nt][1] + h0);
                float v10 = clip6(s8 * acc[mt][nt][2] + h8);
                float v11 = clip6(s8 * acc[mt][nt][3] + h8);
                if (p < HW) {
                    *(__half2*)(hp0 + p) = __floats2half2_rn(v00, v01);
                    *(__half2*)(hp8 + p) = __floats2half2_rn(v10, v11);
                    rs0 += v00 + v01; rs8 += v10 + v11;
                }
            }
            rs0 += __shfl_xor_sync(0xffffffffu, rs0, 1);
            rs0 += __shfl_xor_sync(0xffffffffu, rs0, 2);
            rs8 += __shfl_xor_sync(0xffffffffu, rs8, 1);
            rs8 += __shfl_xor_sync(0xffffffffu, rs8, 2);
            if (tq == 0) {
                atomicAdd(&g_ctxsum[n * C2 + c0], rs0);
                atomicAdd(&g_ctxsum[n * C2 + c8], rs8);
            }
        }
    }
}

// ---------------- context bias ----------------
__global__ void ctxbias_kernel(const float* __restrict__ wctx)
{
    __shared__ float cs[C2];
    const int n = blockIdx.x;
    const int o = threadIdx.x;
    cs[o] = g_ctxsum[n * C2 + o] * (1.f / (float)HW);
    __syncthreads();
    const float* wr = wctx + o * C2;
    float a = 0.f;
    #pragma unroll 4
    for (int c = 0; c < C2; ++c) a += cs[c] * wr[c];
    g_bias2[n * C2 + o] = g_s2[o] * a + g_sh2[o];
}

// ---------------- depthwise 3x3: packed-half2 smem + sliding window ----------------
__global__ void __launch_bounds__(224) dw_kernel(const float* __restrict__ wdw)
{
    __shared__ uint32_t sp[HW];        // word p = (ch0[p], ch1[p]) fp16 pair
    __shared__ float wd[18];
    __shared__ float bs[2], sc[2];

    const int jw = blockIdx.x;         // channel-pair index 0..191
    const int n  = blockIdx.y;
    const int t  = threadIdx.x;
    const int c0 = 2 * jw;

    const uint4* src0 = (const uint4*)(g_hf + ((size_t)(n * C2 + c0)) * HW);
    const uint4* src1 = (const uint4*)(g_hf + ((size_t)(n * C2 + c0 + 1)) * HW);
    #pragma unroll
    for (int i = t; i < HW / 8; i += 224) {
        uint4 a = src0[i];
        uint4 b = src1[i];
        const uint32_t* aw = (const uint32_t*)&a;
        const uint32_t* bw = (const uint32_t*)&b;
        #pragma unroll
        for (int k = 0; k < 4; ++k) {
            sp[8 * i + 2 * k]     = __byte_perm(aw[k], bw[k], 0x5410);
            sp[8 * i + 2 * k + 1] = __byte_perm(aw[k], bw[k], 0x7632);
        }
    }
    if (t < 18) wd[t] = wdw[c0 * 9 + t];
    if (t < 2)  { bs[t] = g_bias2[n * C2 + c0 + t]; sc[t] = g_s2[c0 + t]; }
    __syncthreads();

    const int col  = t % HH;
    const int q    = t / HH;
    const int rbeg = q * 14;
    const bool cl = (col > 0), cr = (col < HH - 1);
    uint32_t* op = g_h2 + ((size_t)(n * 192 + jw)) * HW;
    const float b0 = bs[0], b1 = bs[1], s0 = sc[0], s1 = sc[1];

    float2 pl, pm, pr, cl2, cm, cr2;
    const float2 z2 = make_float2(0.f, 0.f);

    if (rbeg > 0) {
        const uint32_t* rp = sp + (rbeg - 1) * HH + col;
        pl = cl ? __half22float2(*(const __half2*)&rp[-1]) : z2;
        pm = __half22float2(*(const __half2*)&rp[0]);
        pr = cr ? __half22float2(*(const __half2*)&rp[1]) : z2;
    } else { pl = pm = pr = z2; }
    {
        const uint32_t* rc = sp + rbeg * HH + col;
        cl2 = cl ? __half22float2(*(const __half2*)&rc[-1]) : z2;
        cm  = __half22float2(*(const __half2*)&rc[0]);
        cr2 = cr ? __half22float2(*(const __half2*)&rc[1]) : z2;
    }

    #pragma unroll
    for (int j = 0; j < 14; ++j) {
        const int r  = rbeg + j;
        const int nr = r + 1;
        float2 nl, nm, nr2;
        if (nr < HH) {
            const uint32_t* rn = sp + nr * HH + col;
            nl  = cl ? __half22float2(*(const __half2*)&rn[-1]) : z2;
            nm  = __half22float2(*(const __half2*)&rn[0]);
            nr2 = cr ? __half22float2(*(const __half2*)&rn[1]) : z2;
        } else { nl = nm = nr2 = z2; }
        float a0 = pl.x * wd[0] + pm.x * wd[1] + pr.x * wd[2]
                 + cl2.x * wd[3] + cm.x * wd[4] + cr2.x * wd[5]
                 + nl.x * wd[6] + nm.x * wd[7] + nr2.x * wd[8];
        float a1 = pl.y * wd[9]  + pm.y * wd[10] + pr.y * wd[11]
                 + cl2.y * wd[12] + cm.y * wd[13] + cr2.y * wd[14]
                 + nl.y * wd[15] + nm.y * wd[16] + nr2.y * wd[17];
        float v0 = clip6(s0 * a0 + b0);
        float v1 = clip6(s1 * a1 + b1);
        op[r * HH + col] = hpack2(v0, v1);
        pl = cl2; pm = cm; pr = cr2;
        cl2 = nl; cm = nm; cr2 = nr2;
    }
}

// ======================= PROJECT: resident W + cp.async double-buffered X ================
#define XTILE (128 * XS)          // 4608 words per X buffer
#define WCH   (64 * XS)           // 2304 words per W chunk tile
__global__ void __launch_bounds__(256, 2) project_kernel(const float* __restrict__ x,
                                                         float* __restrict__ out)
{
    extern __shared__ uint32_t sm[];
    uint32_t* xsh = sm;                    // [2][128 px][XS] double buffer
    uint32_t* wsh = sm + 2 * XTILE;        // [6][64 ch][XS] full W, pre-chunked

    const int n    = blockIdx.y;
    const int pix0 = blockIdx.x * 128;
    const int tid  = threadIdx.x;
    const int wid  = tid >> 5;
    const int lane = tid & 31;
    const int g    = lane >> 2;
    const int tq   = lane & 3;
    const int wm   = wid & 1;
    const int wn   = wid >> 1;

    const uint32_t xshb = (uint32_t)__cvta_generic_to_shared(xsh);
    const uint32_t wshb = (uint32_t)__cvta_generic_to_shared(wsh);
    const int lrow = (lane & 7) + ((lane >> 3) & 1) * 8;
    const int loff = (lrow * XS + ((lane >> 4) * 4)) * 4;

    // full W: 3072 uint4; word 4i = c*192 + w, w = kt*32 + j
    {
        const uint4* src = (const uint4*)g_wph;
        for (int i = tid; i < 3072; i += 256) {
            int c = i / 48;
            int w = (i % 48) * 4;
            int kt = w >> 5, j = w & 31;
            *(uint4*)&wsh[kt * WCH + c * XS + j] = src[i];
        }
    }

    const uint32_t* hbase = g_h2 + (size_t)n * 192 * HW;

    // prefetch X chunk 0 into buffer 0
    #pragma unroll 1
    for (int idx = tid; idx < 128 * 32; idx += 256) {
        int j = idx >> 7, p = idx & 127;
        int pg = pix0 + p;
        bool v = pg < HW;
        const uint32_t* gp = hbase + (size_t)j * HW + (v ? pg : 0);
        cpasync4(xshb + (uint32_t)(p * XS + j) * 4, gp, v);
    }
    cpasync_commit();

    float acc[2][4][4];
    #pragma unroll
    for (int mt = 0; mt < 2; ++mt)
        #pragma unroll
        for (int nt = 0; nt < 4; ++nt)
            #pragma unroll
            for (int i = 0; i < 4; ++i) acc[mt][nt][i] = 0.f;

    #pragma unroll 1
    for (int kt = 0; kt < 6; ++kt) {
        const int buf = kt & 1;
        if (kt < 5) {
            const int nb = (kt + 1) & 1;
            const uint32_t* hb = hbase + (size_t)(kt + 1) * 32 * HW;
            #pragma unroll 1
            for (int idx = tid; idx < 128 * 32; idx += 256) {
                int j = idx >> 7, p = idx & 127;
                int pg = pix0 + p;
                bool v = pg < HW;
                const uint32_t* gp = hb + (size_t)j * HW + (v ? pg : 0);
                cpasync4(xshb + (uint32_t)(nb * XTILE + p * XS + j) * 4, gp, v);
            }
            cpasync_commit();
            asm volatile("cp.async.wait_group 1;" ::: "memory");
        } else {
            asm volatile("cp.async.wait_group 0;" ::: "memory");
        }
        __syncthreads();

        const uint32_t xb = xshb + (uint32_t)(buf * XTILE) * 4;
        const uint32_t wb = wshb + (uint32_t)(kt * WCH) * 4;
        #pragma unroll
        for (int s = 0; s < 4; ++s) {
            const int soff = s * 32;
            uint32_t ah[2][4], bh[2][4];
            #pragma unroll
            for (int mt = 0; mt < 2; ++mt) {
                uint32_t off = (uint32_t)((wm * 32 + mt * 16) * XS * 4 + soff) + loff;
                ldsm4(ah[mt], wb + off);
            }
            #pragma unroll
            for (int q = 0; q < 2; ++q) {
                uint32_t off = (uint32_t)((wn * 32 + q * 16) * XS * 4 + soff) + loff;
                ldsm4(bh[q], xb + off);
            }
            #pragma unroll
            for (int mt = 0; mt < 2; ++mt)
                #pragma unroll
                for (int q = 0; q < 2; ++q) {
                    mma16816(acc[mt][2*q],   ah[mt], bh[q][0], bh[q][2]);
                    mma16816(acc[mt][2*q+1], ah[mt], bh[q][1], bh[q][3]);
                }
        }
        __syncthreads();
    }

    // epilogue: BN3 + residual
    #pragma unroll
    for (int mt = 0; mt < 2; ++mt) {
        int c0 = wm * 32 + mt * 16 + g;
        int c8 = c0 + 8;
        float s0 = g_s3[c0], h0 = g_sh3[c0];
        float s8 = g_s3[c8], h8 = g_sh3[c8];
        const float* xp0 = x   + ((size_t)(n * C1 + c0)) * HW;
        const float* xp8 = x   + ((size_t)(n * C1 + c8)) * HW;
        float*       op0 = out + ((size_t)(n * C1 + c0)) * HW;
        float*       op8 = out + ((size_t)(n * C1 + c8)) * HW;
        #pragma unroll
        for (int nt = 0; nt < 4; ++nt) {
            int p = pix0 + wn * 32 + nt * 8 + 2 * tq;
            if (p < HW) {
                float2 r0 = *(const float2*)(xp0 + p);
                float2 r8 = *(const float2*)(xp8 + p);
                *(float2*)(op0 + p) = make_float2(s0 * acc[mt][nt][0] + h0 + r0.x,
                                                  s0 * acc[mt][nt][1] + h0 + r0.y);
                *(float2*)(op8 + p) = make_float2(s8 * acc[mt][nt][2] + h8 + r8.x,
                                                  s8 * acc[mt][nt][3] + h8 + r8.y);
            }
        }
    }
}

// ---------------- launch ----------------
extern "C" void kernel_launch(void* const* d_in, const int* in_sizes, int n_in,
                              void* d_out, int out_size)
{
    const float* x        = (const float*)d_in[0];
    const float* w_expand = (const float*)d_in[1];
    const float* g1 = (const float*)d_in[2];
    const float* b1 = (const float*)d_in[3];
    const float* m1 = (const float*)d_in[4];
    const float* v1 = (const float*)d_in[5];
    const float* w_dw  = (const float*)d_in[6];
    const float* w_ctx = (const float*)d_in[7];
    const float* g2 = (const float*)d_in[8];
    const float* b2 = (const float*)d_in[9];
    const float* m2 = (const float*)d_in[10];
    const float* v2 = (const float*)d_in[11];
    const float* w_proj = (const float*)d_in[12];
    const float* g3 = (const float*)d_in[13];
    const float* b3 = (const float*)d_in[14];
    const float* m3 = (const float*)d_in[15];
    const float* v3 = (const float*)d_in[16];
    float* out = (float*)d_out;

    const int smem_expand  = (128 * XS + 384 * XS) * (int)sizeof(uint32_t);      // 73728
    const int smem_project = (2 * XTILE + 6 * WCH) * (int)sizeof(uint32_t);      // 92160
    cudaFuncSetAttribute((const void*)expand_kernel,
                         cudaFuncAttributeMaxDynamicSharedMemorySize, smem_expand);
    cudaFuncSetAttribute((const void*)project_kernel,
                         cudaFuncAttributeMaxDynamicSharedMemorySize, smem_project);

    prep_kernel<<<1, 512>>>(g1, b1, m1, v1, g2, b2, m2, v2, g3, b3, m3, v3,
                            w_expand, w_proj);
    expand_kernel<<<dim3(25, NB), 256, smem_expand>>>(x);
    ctxbias_kernel<<<NB, C2>>>(w_ctx);
    dw_kernel<<<dim3(192, NB), 224>>>(w_dw);
    project_kernel<<<dim3(25, NB), 256, smem_project>>>(x, out);
}